// round 2
// baseline (speedup 1.0000x reference)
#include <cuda_runtime.h>
#include <cuda_bf16.h>

// ---------------------------------------------------------------------------
// C2fDA: cv1(1x1) -> split -> 4x conv3x3 -> msdeform attn -> concat -> cv2(1x1)
// B=8, C1=512, C=256, D=256, NH=8, NP=4, NL=1, H=W=64, L=4096
// ---------------------------------------------------------------------------

#define NB 8
#define HWN 4096            // H*W
#define CATC 1280           // concat channels: [a(256) b(256) b1(256) b2(256) attn(256)]

// Static scratch (allocation-guard-safe)
__device__ float g_cat [(size_t)NB * CATC * HWN];   // (B,1280,4096)
__device__ float g_s0  [(size_t)NB * 256 * HWN];    // conv intermediate
__device__ float g_val [(size_t)NB * HWN * 256];    // value (B,L,NH*32)
__device__ float g_off [(size_t)NB * HWN * 64];     // offsets (B,L,NH*NP*2)
__device__ float g_aw  [(size_t)NB * HWN * 32];     // attn logits (B,L,NH*NP)
__device__ float g_smp [(size_t)NB * HWN * 256];    // sampled (B,L,256)

__device__ __forceinline__ float silu_f(float x) { return x / (1.f + __expf(-x)); }

// ---------------------------------------------------------------------------
// Generic tiled GEMM: C[m][n] = act( sum_k A*B + bias )
// AM=0: A[m*lda+k] (row-major MxK)      AM=1: A[k*lda+m] (KxM)
// BM=0: B[k*ldb+n] (KxN)                BM=1: B[n*ldb+k] (NxK)
// BIAS: 0 none, 1 bias[n], 2 bias[m]
// 64x64 tile, BK=16, 256 threads, 4x4 microtile. K must be a multiple of 16.
// ---------------------------------------------------------------------------
template<int AM, int BM, int BIAS, bool SILU>
__global__ void __launch_bounds__(256) gemm_k(
    const float* __restrict__ A, const float* __restrict__ B,
    const float* __restrict__ bias, float* __restrict__ C,
    int M, int N, int K, int lda, int ldb, int ldc,
    long sA, long sB, long sC)
{
    __shared__ float As[16][64];
    __shared__ float Bs[16][64];
    const int t  = threadIdx.x;
    const int tx = t & 15, ty = t >> 4;
    const int n0 = blockIdx.x * 64, m0 = blockIdx.y * 64;
    const int bz = blockIdx.z;
    A += (size_t)bz * sA; B += (size_t)bz * sB; C += (size_t)bz * sC;

    float acc[4][4] = {};
    for (int k0 = 0; k0 < K; k0 += 16) {
        if (AM == 0) {
            int m = t >> 2, kq = (t & 3) * 4;
            float4 v = make_float4(0.f, 0.f, 0.f, 0.f);
            if (m0 + m < M) v = *(const float4*)(A + (size_t)(m0 + m) * lda + k0 + kq);
            As[kq + 0][m] = v.x; As[kq + 1][m] = v.y;
            As[kq + 2][m] = v.z; As[kq + 3][m] = v.w;
        } else {
            #pragma unroll
            for (int r = 0; r < 4; r++) {
                int i = t + 256 * r; int k = i >> 6, m = i & 63;
                As[k][m] = (m0 + m < M) ? A[(size_t)(k0 + k) * lda + m0 + m] : 0.f;
            }
        }
        if (BM == 0) {
            #pragma unroll
            for (int r = 0; r < 4; r++) {
                int i = t + 256 * r; int k = i >> 6, n = i & 63;
                Bs[k][n] = (n0 + n < N) ? B[(size_t)(k0 + k) * ldb + n0 + n] : 0.f;
            }
        } else {
            int n = t >> 2, kq = (t & 3) * 4;
            float4 v = make_float4(0.f, 0.f, 0.f, 0.f);
            if (n0 + n < N) v = *(const float4*)(B + (size_t)(n0 + n) * ldb + k0 + kq);
            Bs[kq + 0][n] = v.x; Bs[kq + 1][n] = v.y;
            Bs[kq + 2][n] = v.z; Bs[kq + 3][n] = v.w;
        }
        __syncthreads();
        #pragma unroll
        for (int kk = 0; kk < 16; kk++) {
            float4 a = *(const float4*)&As[kk][ty * 4];
            float4 b = *(const float4*)&Bs[kk][tx * 4];
            float av[4] = {a.x, a.y, a.z, a.w};
            float bv[4] = {b.x, b.y, b.z, b.w};
            #pragma unroll
            for (int i = 0; i < 4; i++)
                #pragma unroll
                for (int j = 0; j < 4; j++)
                    acc[i][j] += av[i] * bv[j];
        }
        __syncthreads();
    }
    #pragma unroll
    for (int i = 0; i < 4; i++) {
        int m = m0 + ty * 4 + i;
        if (m >= M) continue;
        #pragma unroll
        for (int j = 0; j < 4; j++) {
            int n = n0 + tx * 4 + j;
            if (n >= N) continue;
            float v = acc[i][j];
            if (BIAS == 1) v += bias[n];
            if (BIAS == 2) v += bias[m];
            if (SILU) v = silu_f(v);
            C[(size_t)m * ldc + n] = v;
        }
    }
}

// ---------------------------------------------------------------------------
// Direct 3x3 conv (pad 1) + SiLU, 256->256 channels, 64x64 spatial.
// Block: (coBlk of 64 out-ch) x (one row y) x (batch). 256 threads,
// microtile 4 co x 4 x per thread. Implicit GEMM over K = 256*9.
// ---------------------------------------------------------------------------
__global__ void __launch_bounds__(256) conv3x3_silu_k(
    const float* __restrict__ in, const float* __restrict__ w,
    float* __restrict__ out, long inStrideB, long outStrideB)
{
    __shared__ float ws[72][64];     // [ci*9 + dy*3+dx][co]
    __shared__ float ins[8][3][68];  // [ci][dy][x+1], zero-padded
    const int t  = threadIdx.x;
    const int tx = t & 15, ty = t >> 4;
    const int coBlk = blockIdx.x;    // 0..3
    const int y = blockIdx.y;        // 0..63
    const int n = blockIdx.z;        // 0..7
    const float* inB = in + (size_t)n * inStrideB;

    float acc[4][4] = {};
    for (int ci0 = 0; ci0 < 256; ci0 += 8) {
        for (int i = t; i < 4608; i += 256) {
            int co = i / 72, q = i - co * 72;
            ws[q][co] = w[(size_t)(coBlk * 64 + co) * 2304 + ci0 * 9 + q];
        }
        for (int i = t; i < 1632; i += 256) {
            int ci = i / 204; int rem = i - ci * 204;
            int dy = rem / 68; int xx = rem - dy * 68;
            int yy = y + dy - 1; int x = xx - 1;
            float v = 0.f;
            if (yy >= 0 && yy < 64 && x >= 0 && x < 64)
                v = inB[(size_t)(ci0 + ci) * HWN + yy * 64 + x];
            ins[ci][dy][xx] = v;
        }
        __syncthreads();
        #pragma unroll
        for (int ci = 0; ci < 8; ci++)
            #pragma unroll
            for (int dy = 0; dy < 3; dy++)
                #pragma unroll
                for (int dx = 0; dx < 3; dx++) {
                    float4 a = *(const float4*)&ws[ci * 9 + dy * 3 + dx][ty * 4];
                    float av[4] = {a.x, a.y, a.z, a.w};
                    float bv[4];
                    #pragma unroll
                    for (int j = 0; j < 4; j++) bv[j] = ins[ci][dy][tx + 16 * j + dx];
                    #pragma unroll
                    for (int i = 0; i < 4; i++)
                        #pragma unroll
                        for (int j = 0; j < 4; j++)
                            acc[i][j] += av[i] * bv[j];
                }
        __syncthreads();
    }
    float* outB = out + (size_t)n * outStrideB + (size_t)y * 64;
    #pragma unroll
    for (int i = 0; i < 4; i++) {
        int co = coBlk * 64 + ty * 4 + i;
        #pragma unroll
        for (int j = 0; j < 4; j++) {
            int x = tx + 16 * j;
            outB[(size_t)co * HWN + x] = silu_f(acc[i][j]);
        }
    }
}

// ---------------------------------------------------------------------------
// Deformable sampling: warp per (b, head, l); lane = dh. Softmax over NP=4
// in-register; 4 bilinear taps, each a coalesced 128B gather from value.
// value: (B, L, NH*32); off: (B,L,NH*NP*2); aw logits: (B,L,NH*NP);
// bbox: (B,L,1,2); samp out: (B,L,256)
// ---------------------------------------------------------------------------
__global__ void __launch_bounds__(256) msda_sample_k(
    const float* __restrict__ value, const float* __restrict__ off,
    const float* __restrict__ awraw, const float* __restrict__ bbox,
    float* __restrict__ samp)
{
    const int bl   = blockIdx.x;            // b*4096 + l
    const int h    = threadIdx.x >> 5;      // head 0..7
    const int lane = threadIdx.x & 31;      // dh
    const float* offp = off + (size_t)bl * 64 + h * 8;
    const float* awp  = awraw + (size_t)bl * 32 + h * 4;
    const float bx = bbox[(size_t)bl * 2 + 0];
    const float by = bbox[(size_t)bl * 2 + 1];

    float a0 = awp[0], a1 = awp[1], a2 = awp[2], a3 = awp[3];
    float mx = fmaxf(fmaxf(a0, a1), fmaxf(a2, a3));
    float e0 = __expf(a0 - mx), e1 = __expf(a1 - mx);
    float e2 = __expf(a2 - mx), e3 = __expf(a3 - mx);
    float inv = 1.f / (e0 + e1 + e2 + e3);
    float awv[4] = {e0 * inv, e1 * inv, e2 * inv, e3 * inv};

    const int b = bl >> 12;
    const float* vb = value + (size_t)b * HWN * 256 + h * 32 + lane;
    float acc = 0.f;
    #pragma unroll
    for (int p = 0; p < 4; p++) {
        float gx = (bx + offp[p * 2 + 0] * (1.f / 64.f)) * 64.f - 0.5f;
        float gy = (by + offp[p * 2 + 1] * (1.f / 64.f)) * 64.f - 0.5f;
        float x0f = floorf(gx), y0f = floorf(gy);
        float wx1 = gx - x0f, wy1 = gy - y0f;
        float wx0 = 1.f - wx1, wy0 = 1.f - wy1;
        int x0 = (int)x0f, y0 = (int)y0f;
        float s = 0.f;
        if ((unsigned)x0 < 64u && (unsigned)y0 < 64u)
            s += wx0 * wy0 * vb[(size_t)(y0 * 64 + x0) * 256];
        if ((unsigned)(x0 + 1) < 64u && (unsigned)y0 < 64u)
            s += wx1 * wy0 * vb[(size_t)(y0 * 64 + x0 + 1) * 256];
        if ((unsigned)x0 < 64u && (unsigned)(y0 + 1) < 64u)
            s += wx0 * wy1 * vb[(size_t)((y0 + 1) * 64 + x0) * 256];
        if ((unsigned)(x0 + 1) < 64u && (unsigned)(y0 + 1) < 64u)
            s += wx1 * wy1 * vb[(size_t)((y0 + 1) * 64 + x0 + 1) * 256];
        acc += awv[p] * s;
    }
    samp[(size_t)bl * 256 + h * 32 + lane] = acc;
}

// ---------------------------------------------------------------------------
extern "C" void kernel_launch(void* const* d_in, const int* in_sizes, int n_in,
                              void* d_out, int out_size)
{
    const float* x       = (const float*)d_in[0];
    const float* bbox    = (const float*)d_in[1];
    // d_in[2]: value_shapes (always [[64,64]]) — unused
    const float* cv1_w   = (const float*)d_in[3];
    const float* m0c1    = (const float*)d_in[4];
    const float* m0c2    = (const float*)d_in[5];
    const float* m1c1    = (const float*)d_in[6];
    const float* m1c2    = (const float*)d_in[7];
    const float* vproj_w = (const float*)d_in[8];
    const float* vproj_b = (const float*)d_in[9];
    const float* off_w   = (const float*)d_in[10];
    const float* off_b   = (const float*)d_in[11];
    const float* aw_w    = (const float*)d_in[12];
    const float* aw_b    = (const float*)d_in[13];
    const float* out_w   = (const float*)d_in[14];
    const float* out_b   = (const float*)d_in[15];
    const float* cv2_w   = (const float*)d_in[16];
    float* out = (float*)d_out;

    float *cat, *s0, *val, *offb, *awb, *smp;
    cudaGetSymbolAddress((void**)&cat,  g_cat);
    cudaGetSymbolAddress((void**)&s0,   g_s0);
    cudaGetSymbolAddress((void**)&val,  g_val);
    cudaGetSymbolAddress((void**)&offb, g_off);
    cudaGetSymbolAddress((void**)&awb,  g_aw);
    cudaGetSymbolAddress((void**)&smp,  g_smp);

    const long SC = (long)CATC * HWN;         // cat batch stride
    const long SI = 256L * HWN;               // 256-ch tensor batch stride

    // 1) cv1 1x1 + SiLU: channels 0..511 of cat = [a | b]
    gemm_k<0, 0, 0, true><<<dim3(64, 8, NB), 256>>>(
        cv1_w, x, nullptr, cat, 512, HWN, 512, 512, HWN, HWN, 0, 512L * HWN, SC);

    // 2-5) bottleneck 3x3 convs (+SiLU): b -> b1 -> b2, in/out of cat slices
    conv3x3_silu_k<<<dim3(4, 64, NB), 256>>>(cat + 256 * HWN, m0c1, s0, SC, SI);
    conv3x3_silu_k<<<dim3(4, 64, NB), 256>>>(s0, m0c2, cat + 512 * HWN, SI, SC);
    conv3x3_silu_k<<<dim3(4, 64, NB), 256>>>(cat + 512 * HWN, m1c1, s0, SC, SI);
    conv3x3_silu_k<<<dim3(4, 64, NB), 256>>>(s0, m1c2, cat + 768 * HWN, SI, SC);

    // 6-8) q projections (q = b2 read channel-major: TN GEMM), bias per-n
    gemm_k<1, 0, 1, false><<<dim3(4, 64, NB), 256>>>(
        cat + 768 * HWN, vproj_w, vproj_b, val, HWN, 256, 256, HWN, 256, 256, SC, 0, 4096L * 256);
    gemm_k<1, 0, 1, false><<<dim3(1, 64, NB), 256>>>(
        cat + 768 * HWN, off_w, off_b, offb, HWN, 64, 256, HWN, 64, 64, SC, 0, 4096L * 64);
    gemm_k<1, 0, 1, false><<<dim3(1, 64, NB), 256>>>(
        cat + 768 * HWN, aw_w, aw_b, awb, HWN, 32, 256, HWN, 32, 32, SC, 0, 4096L * 32);

    // 9) deformable bilinear sampling + softmax-weighted sum over points
    msda_sample_k<<<NB * HWN, 256>>>(val, offb, awb, bbox, smp);

    // 10) output projection, written transposed into cat attn slice (TT GEMM),
    //     bias per-m (= per output channel)
    gemm_k<1, 1, 2, false><<<dim3(64, 4, NB), 256>>>(
        out_w, smp, out_b, cat + 1024 * HWN, 256, HWN, 256, 256, 256, HWN, 0, 4096L * 256, SC);

    // 11) cv2 1x1 + SiLU over concat (K=1280)
    gemm_k<0, 0, 0, true><<<dim3(64, 8, NB), 256>>>(
        cv2_w, cat, nullptr, out, 512, HWN, 1280, 1280, HWN, HWN, 0, SC, 512L * HWN);
}

// round 3
// speedup vs baseline: 1.4182x; 1.4182x over previous
#include <cuda_runtime.h>
#include <cuda_bf16.h>

// ---------------------------------------------------------------------------
// C2fDA: cv1(1x1) -> split -> 4x conv3x3 -> msdeform attn -> concat -> cv2(1x1)
// B=8, C1=512, C=256, D=256, NH=8, NP=4, NL=1, H=W=64, L=4096
// ---------------------------------------------------------------------------

#define NB 8
#define HWN 4096            // H*W
#define CATC 1280           // concat channels: [a(256) b(256) b1(256) b2(256) attn(256)]

// Static scratch (allocation-guard-safe)
__device__ float g_cat [(size_t)NB * CATC * HWN];   // (B,1280,4096)
__device__ float g_s0  [(size_t)NB * 256 * HWN];    // conv intermediate
__device__ float g_val [(size_t)NB * HWN * 256];    // value (B,L,NH*32)
__device__ float g_off [(size_t)NB * HWN * 64];     // offsets (B,L,NH*NP*2)
__device__ float g_aw  [(size_t)NB * HWN * 32];     // attn logits (B,L,NH*NP)
__device__ float g_smp [(size_t)NB * HWN * 256];    // sampled (B,L,256)

__device__ __forceinline__ float silu_f(float x) { return x / (1.f + __expf(-x)); }

// ---------------------------------------------------------------------------
// 128x128 tiled GEMM, BK=16, 256 threads, 8x8 microtile (4+4 split layout).
// AM=0: A[m*lda+k] (MxK)    AM=1: A[k*lda+m] (KxM)
// BM=0: B[k*ldb+n] (KxN)    BM=1: B[n*ldb+k] (NxK)
// BIAS: 0 none, 1 bias[n], 2 bias[m].  K % 16 == 0. M,N % 4 == 0 assumed for
// float4 stores (all call sites have M,N multiples of 128).
// ---------------------------------------------------------------------------
template<int AM, int BM, int BIAS, bool SILU>
__global__ void __launch_bounds__(256) gemm128_k(
    const float* __restrict__ A, const float* __restrict__ B,
    const float* __restrict__ bias, float* __restrict__ C,
    int M, int N, int K, int lda, int ldb, int ldc,
    long sA, long sB, long sC)
{
    __shared__ float As[16][132];
    __shared__ float Bs[16][132];
    const int t  = threadIdx.x;
    const int tx = t & 15, ty = t >> 4;
    const int n0 = blockIdx.x * 128, m0 = blockIdx.y * 128;
    A += (size_t)blockIdx.z * sA; B += (size_t)blockIdx.z * sB;
    C += (size_t)blockIdx.z * sC;

    float acc[8][8] = {};
    for (int k0 = 0; k0 < K; k0 += 16) {
        #pragma unroll
        for (int r = 0; r < 2; r++) {
            int idx = t + 256 * r;
            if (AM == 0) {
                int m = idx >> 2, kq = (idx & 3) * 4;
                float4 v = make_float4(0.f, 0.f, 0.f, 0.f);
                if (m0 + m < M) v = *(const float4*)(A + (size_t)(m0 + m) * lda + k0 + kq);
                As[kq + 0][m] = v.x; As[kq + 1][m] = v.y;
                As[kq + 2][m] = v.z; As[kq + 3][m] = v.w;
            } else {
                int k = idx >> 5, c4 = (idx & 31) * 4;
                float4 v = make_float4(0.f, 0.f, 0.f, 0.f);
                if (m0 + c4 < M) v = *(const float4*)(A + (size_t)(k0 + k) * lda + m0 + c4);
                *(float4*)&As[k][c4] = v;
            }
        }
        #pragma unroll
        for (int r = 0; r < 2; r++) {
            int idx = t + 256 * r;
            if (BM == 0) {
                int k = idx >> 5, c4 = (idx & 31) * 4;
                float4 v = make_float4(0.f, 0.f, 0.f, 0.f);
                if (n0 + c4 < N) v = *(const float4*)(B + (size_t)(k0 + k) * ldb + n0 + c4);
                *(float4*)&Bs[k][c4] = v;
            } else {
                int n = idx >> 2, kq = (idx & 3) * 4;
                float4 v = make_float4(0.f, 0.f, 0.f, 0.f);
                if (n0 + n < N) v = *(const float4*)(B + (size_t)(n0 + n) * ldb + k0 + kq);
                Bs[kq + 0][n] = v.x; Bs[kq + 1][n] = v.y;
                Bs[kq + 2][n] = v.z; Bs[kq + 3][n] = v.w;
            }
        }
        __syncthreads();
        #pragma unroll
        for (int kk = 0; kk < 16; kk++) {
            float4 a0 = *(const float4*)&As[kk][ty * 4];
            float4 a1 = *(const float4*)&As[kk][64 + ty * 4];
            float4 b0 = *(const float4*)&Bs[kk][tx * 4];
            float4 b1 = *(const float4*)&Bs[kk][64 + tx * 4];
            float av[8] = {a0.x, a0.y, a0.z, a0.w, a1.x, a1.y, a1.z, a1.w};
            float bv[8] = {b0.x, b0.y, b0.z, b0.w, b1.x, b1.y, b1.z, b1.w};
            #pragma unroll
            for (int i = 0; i < 8; i++)
                #pragma unroll
                for (int j = 0; j < 8; j++)
                    acc[i][j] += av[i] * bv[j];
        }
        __syncthreads();
    }
    #pragma unroll
    for (int i = 0; i < 8; i++) {
        int m = m0 + (i < 4 ? ty * 4 + i : 64 + ty * 4 + (i - 4));
        if (m >= M) continue;
        float bm = (BIAS == 2) ? bias[m] : 0.f;
        #pragma unroll
        for (int jh = 0; jh < 2; jh++) {
            int n = n0 + jh * 64 + tx * 4;
            if (n >= N) continue;
            float vv[4];
            #pragma unroll
            for (int j = 0; j < 4; j++) {
                float u = acc[i][jh * 4 + j];
                if (BIAS == 1) u += bias[n + j];
                if (BIAS == 2) u += bm;
                if (SILU) u = silu_f(u);
                vv[j] = u;
            }
            *(float4*)(C + (size_t)m * ldc + n) =
                make_float4(vv[0], vv[1], vv[2], vv[3]);
        }
    }
}

// ---------------------------------------------------------------------------
// Old 64x64 GEMM kept for the small N=64/32 projections.
// ---------------------------------------------------------------------------
template<int AM, int BM, int BIAS, bool SILU>
__global__ void __launch_bounds__(256) gemm_k(
    const float* __restrict__ A, const float* __restrict__ B,
    const float* __restrict__ bias, float* __restrict__ C,
    int M, int N, int K, int lda, int ldb, int ldc,
    long sA, long sB, long sC)
{
    __shared__ float As[16][64];
    __shared__ float Bs[16][64];
    const int t  = threadIdx.x;
    const int tx = t & 15, ty = t >> 4;
    const int n0 = blockIdx.x * 64, m0 = blockIdx.y * 64;
    const int bz = blockIdx.z;
    A += (size_t)bz * sA; B += (size_t)bz * sB; C += (size_t)bz * sC;

    float acc[4][4] = {};
    for (int k0 = 0; k0 < K; k0 += 16) {
        if (AM == 0) {
            int m = t >> 2, kq = (t & 3) * 4;
            float4 v = make_float4(0.f, 0.f, 0.f, 0.f);
            if (m0 + m < M) v = *(const float4*)(A + (size_t)(m0 + m) * lda + k0 + kq);
            As[kq + 0][m] = v.x; As[kq + 1][m] = v.y;
            As[kq + 2][m] = v.z; As[kq + 3][m] = v.w;
        } else {
            #pragma unroll
            for (int r = 0; r < 4; r++) {
                int i = t + 256 * r; int k = i >> 6, m = i & 63;
                As[k][m] = (m0 + m < M) ? A[(size_t)(k0 + k) * lda + m0 + m] : 0.f;
            }
        }
        if (BM == 0) {
            #pragma unroll
            for (int r = 0; r < 4; r++) {
                int i = t + 256 * r; int k = i >> 6, n = i & 63;
                Bs[k][n] = (n0 + n < N) ? B[(size_t)(k0 + k) * ldb + n0 + n] : 0.f;
            }
        } else {
            int n = t >> 2, kq = (t & 3) * 4;
            float4 v = make_float4(0.f, 0.f, 0.f, 0.f);
            if (n0 + n < N) v = *(const float4*)(B + (size_t)(n0 + n) * ldb + k0 + kq);
            Bs[kq + 0][n] = v.x; Bs[kq + 1][n] = v.y;
            Bs[kq + 2][n] = v.z; Bs[kq + 3][n] = v.w;
        }
        __syncthreads();
        #pragma unroll
        for (int kk = 0; kk < 16; kk++) {
            float4 a = *(const float4*)&As[kk][ty * 4];
            float4 b = *(const float4*)&Bs[kk][tx * 4];
            float av[4] = {a.x, a.y, a.z, a.w};
            float bv[4] = {b.x, b.y, b.z, b.w};
            #pragma unroll
            for (int i = 0; i < 4; i++)
                #pragma unroll
                for (int j = 0; j < 4; j++)
                    acc[i][j] += av[i] * bv[j];
        }
        __syncthreads();
    }
    #pragma unroll
    for (int i = 0; i < 4; i++) {
        int m = m0 + ty * 4 + i;
        if (m >= M) continue;
        #pragma unroll
        for (int j = 0; j < 4; j++) {
            int n = n0 + tx * 4 + j;
            if (n >= N) continue;
            float v = acc[i][j];
            if (BIAS == 1) v += bias[n];
            if (BIAS == 2) v += bias[m];
            if (SILU) v = silu_f(v);
            C[(size_t)m * ldc + n] = v;
        }
    }
}

// ---------------------------------------------------------------------------
// Direct 3x3 conv (pad 1) + SiLU, 256->256 ch, 64x64 spatial.
// Block: 128 out-ch x one row y x batch. 256 threads, microtile 8co x 4px
// (4+4 split on co). Pixel slab loaded once per (ci,dy), reused across dx.
// ---------------------------------------------------------------------------
__global__ void __launch_bounds__(256) conv3x3_silu_k(
    const float* __restrict__ in, const float* __restrict__ w,
    float* __restrict__ out, long inStrideB, long outStrideB)
{
    __shared__ float ws[72][132];    // [ci*9 + dy*3+dx][co]
    __shared__ float ins[8][3][68];  // [ci][dy][x+1], zero-padded
    const int t  = threadIdx.x;
    const int tx = t & 15, ty = t >> 4;
    const int coBlk = blockIdx.x;    // 0..1
    const int y = blockIdx.y;        // 0..63
    const int n = blockIdx.z;        // 0..7
    const float* inB = in + (size_t)n * inStrideB;

    float acc[8][4] = {};
    for (int ci0 = 0; ci0 < 256; ci0 += 8) {
        for (int i = t; i < 9216; i += 256) {
            int co = i / 72, q = i - co * 72;
            ws[q][co] = w[(size_t)(coBlk * 128 + co) * 2304 + ci0 * 9 + q];
        }
        for (int i = t; i < 1632; i += 256) {
            int ci = i / 204; int rem = i - ci * 204;
            int dy = rem / 68; int xx = rem - dy * 68;
            int yy = y + dy - 1; int x = xx - 1;
            float v = 0.f;
            if (yy >= 0 && yy < 64 && (unsigned)x < 64u)
                v = inB[(size_t)(ci0 + ci) * HWN + yy * 64 + x];
            ins[ci][dy][xx] = v;
        }
        __syncthreads();
        #pragma unroll
        for (int ci = 0; ci < 8; ci++)
            #pragma unroll
            for (int dy = 0; dy < 3; dy++) {
                float4 p4 = *(const float4*)&ins[ci][dy][tx * 4];
                float2 p2 = *(const float2*)&ins[ci][dy][tx * 4 + 4];
                float b6[6] = {p4.x, p4.y, p4.z, p4.w, p2.x, p2.y};
                #pragma unroll
                for (int dx = 0; dx < 3; dx++) {
                    int q = ci * 9 + dy * 3 + dx;
                    float4 a0 = *(const float4*)&ws[q][ty * 4];
                    float4 a1 = *(const float4*)&ws[q][64 + ty * 4];
                    float av[8] = {a0.x, a0.y, a0.z, a0.w,
                                   a1.x, a1.y, a1.z, a1.w};
                    #pragma unroll
                    for (int i2 = 0; i2 < 8; i2++)
                        #pragma unroll
                        for (int j = 0; j < 4; j++)
                            acc[i2][j] += av[i2] * b6[j + dx];
                }
            }
        __syncthreads();
    }
    float* outB = out + (size_t)n * outStrideB + (size_t)y * 64;
    #pragma unroll
    for (int i2 = 0; i2 < 8; i2++) {
        int co = coBlk * 128 + (i2 < 4 ? ty * 4 + i2 : 64 + ty * 4 + (i2 - 4));
        float4 v = make_float4(silu_f(acc[i2][0]), silu_f(acc[i2][1]),
                               silu_f(acc[i2][2]), silu_f(acc[i2][3]));
        *(float4*)(outB + (size_t)co * HWN + tx * 4) = v;
    }
}

// ---------------------------------------------------------------------------
// Deformable sampling: warp per (b, head, l); lane = dh. Softmax over NP=4
// in-register; 4 bilinear taps, each a coalesced 128B gather from value.
// ---------------------------------------------------------------------------
__global__ void __launch_bounds__(256) msda_sample_k(
    const float* __restrict__ value, const float* __restrict__ off,
    const float* __restrict__ awraw, const float* __restrict__ bbox,
    float* __restrict__ samp)
{
    const int bl   = blockIdx.x;            // b*4096 + l
    const int h    = threadIdx.x >> 5;      // head 0..7
    const int lane = threadIdx.x & 31;      // dh
    const float* offp = off + (size_t)bl * 64 + h * 8;
    const float* awp  = awraw + (size_t)bl * 32 + h * 4;
    const float bx = bbox[(size_t)bl * 2 + 0];
    const float by = bbox[(size_t)bl * 2 + 1];

    float a0 = awp[0], a1 = awp[1], a2 = awp[2], a3 = awp[3];
    float mx = fmaxf(fmaxf(a0, a1), fmaxf(a2, a3));
    float e0 = __expf(a0 - mx), e1 = __expf(a1 - mx);
    float e2 = __expf(a2 - mx), e3 = __expf(a3 - mx);
    float inv = 1.f / (e0 + e1 + e2 + e3);
    float awv[4] = {e0 * inv, e1 * inv, e2 * inv, e3 * inv};

    const int b = bl >> 12;
    const float* vb = value + (size_t)b * HWN * 256 + h * 32 + lane;
    float acc = 0.f;
    #pragma unroll
    for (int p = 0; p < 4; p++) {
        float gx = (bx + offp[p * 2 + 0] * (1.f / 64.f)) * 64.f - 0.5f;
        float gy = (by + offp[p * 2 + 1] * (1.f / 64.f)) * 64.f - 0.5f;
        float x0f = floorf(gx), y0f = floorf(gy);
        float wx1 = gx - x0f, wy1 = gy - y0f;
        float wx0 = 1.f - wx1, wy0 = 1.f - wy1;
        int x0 = (int)x0f, y0 = (int)y0f;
        float s = 0.f;
        if ((unsigned)x0 < 64u && (unsigned)y0 < 64u)
            s += wx0 * wy0 * vb[(size_t)(y0 * 64 + x0) * 256];
        if ((unsigned)(x0 + 1) < 64u && (unsigned)y0 < 64u)
            s += wx1 * wy0 * vb[(size_t)(y0 * 64 + x0 + 1) * 256];
        if ((unsigned)x0 < 64u && (unsigned)(y0 + 1) < 64u)
            s += wx0 * wy1 * vb[(size_t)((y0 + 1) * 64 + x0) * 256];
        if ((unsigned)(x0 + 1) < 64u && (unsigned)(y0 + 1) < 64u)
            s += wx1 * wy1 * vb[(size_t)((y0 + 1) * 64 + x0 + 1) * 256];
        acc += awv[p] * s;
    }
    samp[(size_t)bl * 256 + h * 32 + lane] = acc;
}

// ---------------------------------------------------------------------------
extern "C" void kernel_launch(void* const* d_in, const int* in_sizes, int n_in,
                              void* d_out, int out_size)
{
    const float* x       = (const float*)d_in[0];
    const float* bbox    = (const float*)d_in[1];
    // d_in[2]: value_shapes (always [[64,64]]) — unused
    const float* cv1_w   = (const float*)d_in[3];
    const float* m0c1    = (const float*)d_in[4];
    const float* m0c2    = (const float*)d_in[5];
    const float* m1c1    = (const float*)d_in[6];
    const float* m1c2    = (const float*)d_in[7];
    const float* vproj_w = (const float*)d_in[8];
    const float* vproj_b = (const float*)d_in[9];
    const float* off_w   = (const float*)d_in[10];
    const float* off_b   = (const float*)d_in[11];
    const float* aw_w    = (const float*)d_in[12];
    const float* aw_b    = (const float*)d_in[13];
    const float* out_w   = (const float*)d_in[14];
    const float* out_b   = (const float*)d_in[15];
    const float* cv2_w   = (const float*)d_in[16];
    float* out = (float*)d_out;

    float *cat, *s0, *val, *offb, *awb, *smp;
    cudaGetSymbolAddress((void**)&cat,  g_cat);
    cudaGetSymbolAddress((void**)&s0,   g_s0);
    cudaGetSymbolAddress((void**)&val,  g_val);
    cudaGetSymbolAddress((void**)&offb, g_off);
    cudaGetSymbolAddress((void**)&awb,  g_aw);
    cudaGetSymbolAddress((void**)&smp,  g_smp);

    const long SC = (long)CATC * HWN;         // cat batch stride
    const long SI = 256L * HWN;               // 256-ch tensor batch stride

    // 1) cv1 1x1 + SiLU: channels 0..511 of cat = [a | b]
    gemm128_k<0, 0, 0, true><<<dim3(32, 4, NB), 256>>>(
        cv1_w, x, nullptr, cat, 512, HWN, 512, 512, HWN, HWN, 0, 512L * HWN, SC);

    // 2-5) bottleneck 3x3 convs (+SiLU): b -> b1 -> b2, in/out of cat slices
    conv3x3_silu_k<<<dim3(2, 64, NB), 256>>>(cat + 256 * HWN, m0c1, s0, SC, SI);
    conv3x3_silu_k<<<dim3(2, 64, NB), 256>>>(s0, m0c2, cat + 512 * HWN, SI, SC);
    conv3x3_silu_k<<<dim3(2, 64, NB), 256>>>(cat + 512 * HWN, m1c1, s0, SC, SI);
    conv3x3_silu_k<<<dim3(2, 64, NB), 256>>>(s0, m1c2, cat + 768 * HWN, SI, SC);

    // 6) value projection (q = b2 read channel-major: TN GEMM), bias per-n
    gemm128_k<1, 0, 1, false><<<dim3(2, 32, NB), 256>>>(
        cat + 768 * HWN, vproj_w, vproj_b, val, HWN, 256, 256, HWN, 256, 256,
        SC, 0, 4096L * 256);

    // 7-8) offset / attn-weight projections (small N: keep 64x64 GEMM)
    gemm_k<1, 0, 1, false><<<dim3(1, 64, NB), 256>>>(
        cat + 768 * HWN, off_w, off_b, offb, HWN, 64, 256, HWN, 64, 64,
        SC, 0, 4096L * 64);
    gemm_k<1, 0, 1, false><<<dim3(1, 64, NB), 256>>>(
        cat + 768 * HWN, aw_w, aw_b, awb, HWN, 32, 256, HWN, 32, 32,
        SC, 0, 4096L * 32);

    // 9) deformable bilinear sampling + softmax-weighted sum over points
    msda_sample_k<<<NB * HWN, 256>>>(val, offb, awb, bbox, smp);

    // 10) output projection, written transposed into cat attn slice (TT GEMM)
    gemm128_k<1, 1, 2, false><<<dim3(32, 2, NB), 256>>>(
        out_w, smp, out_b, cat + 1024 * HWN, 256, HWN, 256, 256, 256, HWN,
        0, 4096L * 256, SC);

    // 11) cv2 1x1 + SiLU over concat (K=1280)
    gemm128_k<0, 0, 0, true><<<dim3(32, 4, NB), 256>>>(
        cv2_w, cat, nullptr, out, 512, HWN, 1280, 1280, HWN, HWN, 0, SC,
        512L * HWN);
}

// round 5
// speedup vs baseline: 2.3977x; 1.6906x over previous
#include <cuda_runtime.h>
#include <cuda_bf16.h>
#include <cstdint>

// ---------------------------------------------------------------------------
// C2fDA via legacy HMMA (mma.sync m16n8k16 bf16) — sm_103 base target safe.
// All big matmuls use bf16 hi/lo split-3 (fp32 accum): err ~1e-5.
// B=8, C1=512, C=256, D=256, NH=8, NP=4, NL=1, H=W=64, L=4096
// ---------------------------------------------------------------------------

#define NB 8
#define HWN 4096

// ---------------- scratch (allocation-guard-safe) --------------------------
__device__ uint32_t g_xp_h [(size_t)NB*4096*256];
__device__ uint32_t g_xp_l [(size_t)NB*4096*256];
__device__ uint32_t g_catp_h[(size_t)NB*4096*640];   // [a|b|b1|b2|attn] pairs
__device__ uint32_t g_catp_l[(size_t)NB*4096*640];
__device__ uint32_t g_s0p_h[(size_t)NB*4096*128];
__device__ uint32_t g_s0p_l[(size_t)NB*4096*128];
__device__ uint32_t g_smpp_h[(size_t)NB*4096*128];
__device__ uint32_t g_smpp_l[(size_t)NB*4096*128];
__device__ float    g_val  [(size_t)NB*4096*256];
__device__ float    g_off  [(size_t)NB*4096*64];
__device__ float    g_aw   [(size_t)NB*4096*32];
__device__ uint32_t g_wcv1_h[512*256],  g_wcv1_l[512*256];
__device__ uint32_t g_wcv2_h[512*640],  g_wcv2_l[512*640];
__device__ uint32_t g_wvp_h [256*128],  g_wvp_l [256*128];
__device__ uint32_t g_wop_h [256*128],  g_wop_l [256*128];
__device__ uint32_t g_wc_h  [4][256*1152], g_wc_l[4][256*1152];

__device__ __forceinline__ float silu_f(float x) { return x / (1.f + __expf(-x)); }

__device__ __forceinline__ void hilo16(float v, unsigned short& h, unsigned short& l) {
    __nv_bfloat16 hb = __float2bfloat16(v);
    float res = v - __bfloat162float(hb);
    __nv_bfloat16 lb = __float2bfloat16(res);
    h = __bfloat16_as_ushort(hb); l = __bfloat16_as_ushort(lb);
}
__device__ __forceinline__ void pack2(float v0, float v1, uint32_t& hp, uint32_t& lp) {
    unsigned short h0, l0, h1, l1;
    hilo16(v0, h0, l0); hilo16(v1, h1, l1);
    hp = ((uint32_t)h1 << 16) | h0;
    lp = ((uint32_t)l1 << 16) | l0;
}
__device__ __forceinline__ float unpk_lo(uint32_t u) {
    return __bfloat162float(__ushort_as_bfloat16((unsigned short)(u & 0xffff)));
}
__device__ __forceinline__ float unpk_hi(uint32_t u) {
    return __bfloat162float(__ushort_as_bfloat16((unsigned short)(u >> 16)));
}

// mma.sync m16n8k16 row.col f32.bf16.bf16.f32 (baseline PTX, sm_80+)
__device__ __forceinline__ void mma16816(float* d, const uint32_t* a, const uint32_t* b) {
    asm volatile(
        "mma.sync.aligned.m16n8k16.row.col.f32.bf16.bf16.f32 "
        "{%0,%1,%2,%3}, {%4,%5,%6,%7}, {%8,%9}, {%0,%1,%2,%3};"
        : "+f"(d[0]), "+f"(d[1]), "+f"(d[2]), "+f"(d[3])
        : "r"(a[0]), "r"(a[1]), "r"(a[2]), "r"(a[3]), "r"(b[0]), "r"(b[1]));
}

// ---------------------------------------------------------------------------
// HMMA matmul: D[128 spatial][128 out-ch] per CTA, K-chunk 32 (16 u32 pairs).
// A packed hi/lo [row][kpair]; B (weights) packed hi/lo [co][kpair].
// Smem tiles [kp][row/co] stride 136 -> conflict-free fragment LDS.
// CONV: im2col row shift, K order (dy,dx)-major, 128 ci-pairs per tap.
// OUTM: 0 packed hi/lo out [n][cpair]; 1 fp32 [n][ldoutF]; 2 fp32 [c][ldoutF].
// ---------------------------------------------------------------------------
template<bool CONV, int OUTM, bool SILU, bool BIASF>
__global__ void __launch_bounds__(256) mm_hmma(
    const uint32_t* __restrict__ Ahi, const uint32_t* __restrict__ Alo,
    int ldap, int apbase,
    const uint32_t* __restrict__ Bhi, const uint32_t* __restrict__ Blo, int ldbp,
    const float* __restrict__ bias,
    float* __restrict__ outF, int ldoutF, long outFb,
    uint32_t* __restrict__ Ohi, uint32_t* __restrict__ Olo, int ldop, int opbase,
    int Ktot)
{
    __shared__ uint32_t sAh[16*136], sAl[16*136], sBh[16*136], sBl[16*136];

    const int tid  = threadIdx.x;
    const int lane = tid & 31;
    const int wid  = tid >> 5;
    const int g    = lane >> 2;      // group row/col
    const int t4   = lane & 3;
    const int m0w  = (wid & 1) * 64;
    const int n0w  = (wid >> 1) * 32;
    const int n0 = blockIdx.x * 128, c0 = blockIdx.y * 128, b = blockIdx.z;

    Ahi += (size_t)b * 4096 * ldap;
    Alo += (size_t)b * 4096 * ldap;
    if (OUTM == 0) { Ohi += (size_t)b * 4096 * ldop; Olo += (size_t)b * 4096 * ldop; }
    else           { outF += (size_t)b * outFb; }

    const int rr   = tid & 127;   // loader row (spatial or co)
    const int half = tid >> 7;    // kp half (0/1)

    float acc[4][4][4] = {};
    const int NC = Ktot >> 5;

    for (int ch = 0; ch < NC; ch++) {
        // ---- addressing for this chunk ----
        int srcRow = n0 + rr;
        bool valid = true;
        int cp0;
        if (CONV) {
            const int t9 = ch >> 3;
            const int dy = t9 / 3, dx = t9 - dy * 3;
            cp0 = (ch & 7) * 16;
            const int nn = n0 + rr;
            const int yy = (nn >> 6) + dy - 1, xx = (nn & 63) + dx - 1;
            valid = ((unsigned)yy < 64u) && ((unsigned)xx < 64u);
            srcRow = yy * 64 + xx;
        } else {
            cp0 = ch * 16;
        }
        __syncthreads();   // protect smem from previous iteration's consumers
        {   // A tile: global [row][kp] -> smem [kp][row]
            const uint4 z = make_uint4(0, 0, 0, 0);
            const uint4* pah = (const uint4*)(Ahi + (size_t)srcRow * ldap + apbase + cp0 + half * 8);
            const uint4* pal = (const uint4*)(Alo + (size_t)srcRow * ldap + apbase + cp0 + half * 8);
            uint4 h0 = valid ? pah[0] : z, h1 = valid ? pah[1] : z;
            uint4 l0 = valid ? pal[0] : z, l1 = valid ? pal[1] : z;
            const int kb = half * 8;
            sAh[(kb+0)*136+rr]=h0.x; sAh[(kb+1)*136+rr]=h0.y; sAh[(kb+2)*136+rr]=h0.z; sAh[(kb+3)*136+rr]=h0.w;
            sAh[(kb+4)*136+rr]=h1.x; sAh[(kb+5)*136+rr]=h1.y; sAh[(kb+6)*136+rr]=h1.z; sAh[(kb+7)*136+rr]=h1.w;
            sAl[(kb+0)*136+rr]=l0.x; sAl[(kb+1)*136+rr]=l0.y; sAl[(kb+2)*136+rr]=l0.z; sAl[(kb+3)*136+rr]=l0.w;
            sAl[(kb+4)*136+rr]=l1.x; sAl[(kb+5)*136+rr]=l1.y; sAl[(kb+6)*136+rr]=l1.z; sAl[(kb+7)*136+rr]=l1.w;
        }
        {   // B tile (weights): [co][kp] -> smem [kp][co]
            const int kp0 = ch * 16 + half * 8;
            const uint4* pbh = (const uint4*)(Bhi + (size_t)(c0 + rr) * ldbp + kp0);
            const uint4* pbl = (const uint4*)(Blo + (size_t)(c0 + rr) * ldbp + kp0);
            uint4 h0 = pbh[0], h1 = pbh[1];
            uint4 l0 = pbl[0], l1 = pbl[1];
            const int kb = half * 8;
            sBh[(kb+0)*136+rr]=h0.x; sBh[(kb+1)*136+rr]=h0.y; sBh[(kb+2)*136+rr]=h0.z; sBh[(kb+3)*136+rr]=h0.w;
            sBh[(kb+4)*136+rr]=h1.x; sBh[(kb+5)*136+rr]=h1.y; sBh[(kb+6)*136+rr]=h1.z; sBh[(kb+7)*136+rr]=h1.w;
            sBl[(kb+0)*136+rr]=l0.x; sBl[(kb+1)*136+rr]=l0.y; sBl[(kb+2)*136+rr]=l0.z; sBl[(kb+3)*136+rr]=l0.w;
            sBl[(kb+4)*136+rr]=l1.x; sBl[(kb+5)*136+rr]=l1.y; sBl[(kb+6)*136+rr]=l1.z; sBl[(kb+7)*136+rr]=l1.w;
        }
        __syncthreads();

        #pragma unroll
        for (int ks = 0; ks < 2; ks++) {
            const int kb = ks * 8;
            uint32_t ah[4][4], bh[4][2], bl[4][2];
            #pragma unroll
            for (int mf = 0; mf < 4; mf++) {
                const int r0 = m0w + mf * 16 + g;
                ah[mf][0] = sAh[(kb + t4)     * 136 + r0];
                ah[mf][1] = sAh[(kb + t4)     * 136 + r0 + 8];
                ah[mf][2] = sAh[(kb + t4 + 4) * 136 + r0];
                ah[mf][3] = sAh[(kb + t4 + 4) * 136 + r0 + 8];
            }
            #pragma unroll
            for (int nf = 0; nf < 4; nf++) {
                const int cn = n0w + nf * 8 + g;
                bh[nf][0] = sBh[(kb + t4)     * 136 + cn];
                bh[nf][1] = sBh[(kb + t4 + 4) * 136 + cn];
                bl[nf][0] = sBl[(kb + t4)     * 136 + cn];
                bl[nf][1] = sBl[(kb + t4 + 4) * 136 + cn];
            }
            // pass1: hiA*hiB   pass2: hiA*loB
            #pragma unroll
            for (int mf = 0; mf < 4; mf++)
                #pragma unroll
                for (int nf = 0; nf < 4; nf++) {
                    mma16816(acc[mf][nf], ah[mf], bh[nf]);
                    mma16816(acc[mf][nf], ah[mf], bl[nf]);
                }
            // pass3: loA*hiB (reload A frags from lo tile)
            #pragma unroll
            for (int mf = 0; mf < 4; mf++) {
                const int r0 = m0w + mf * 16 + g;
                ah[mf][0] = sAl[(kb + t4)     * 136 + r0];
                ah[mf][1] = sAl[(kb + t4)     * 136 + r0 + 8];
                ah[mf][2] = sAl[(kb + t4 + 4) * 136 + r0];
                ah[mf][3] = sAl[(kb + t4 + 4) * 136 + r0 + 8];
            }
            #pragma unroll
            for (int mf = 0; mf < 4; mf++)
                #pragma unroll
                for (int nf = 0; nf < 4; nf++)
                    mma16816(acc[mf][nf], ah[mf], bh[nf]);
        }
    }

    // ---- epilogue ----
    #pragma unroll
    for (int mf = 0; mf < 4; mf++) {
        const int r0 = n0 + m0w + mf * 16 + g;
        #pragma unroll
        for (int nf = 0; nf < 4; nf++) {
            const int ncol = c0 + n0w + nf * 8 + t4 * 2;   // even
            float v00 = acc[mf][nf][0], v01 = acc[mf][nf][1];
            float v10 = acc[mf][nf][2], v11 = acc[mf][nf][3];
            if (BIASF) {
                const float b0f = bias[ncol], b1f = bias[ncol + 1];
                v00 += b0f; v01 += b1f; v10 += b0f; v11 += b1f;
            }
            if (SILU) {
                v00 = silu_f(v00); v01 = silu_f(v01);
                v10 = silu_f(v10); v11 = silu_f(v11);
            }
            if (OUTM == 0) {
                uint32_t hp, lp;
                pack2(v00, v01, hp, lp);
                const size_t i0 = (size_t)r0 * ldop + opbase + (ncol >> 1);
                Ohi[i0] = hp; Olo[i0] = lp;
                pack2(v10, v11, hp, lp);
                const size_t i1 = (size_t)(r0 + 8) * ldop + opbase + (ncol >> 1);
                Ohi[i1] = hp; Olo[i1] = lp;
            } else if (OUTM == 1) {
                *(float2*)(outF + (size_t)r0 * ldoutF + ncol)       = make_float2(v00, v01);
                *(float2*)(outF + (size_t)(r0 + 8) * ldoutF + ncol) = make_float2(v10, v11);
            } else {
                outF[(size_t)ncol       * ldoutF + r0]     = v00;
                outF[(size_t)(ncol + 1) * ldoutF + r0]     = v01;
                outF[(size_t)ncol       * ldoutF + r0 + 8] = v10;
                outF[(size_t)(ncol + 1) * ldoutF + r0 + 8] = v11;
            }
        }
    }
}

// ---------------------------------------------------------------------------
// Prepack kernels (unchanged from round 4)
// ---------------------------------------------------------------------------
__global__ void prepack_x_k(const float* __restrict__ x,
                            uint32_t* __restrict__ xh, uint32_t* __restrict__ xl)
{
    __shared__ uint32_t th[32][33], tl[32][33];
    const int tx = threadIdx.x, ty = threadIdx.y;
    const int n0 = blockIdx.x * 32, cp0 = blockIdx.y * 32, b = blockIdx.z;
    const float* xb = x + (size_t)b * 512 * 4096;
    #pragma unroll
    for (int k = 0; k < 4; k++) {
        const int cp = cp0 + ty + k * 8;
        const float v0 = xb[(size_t)(2 * cp) * 4096 + n0 + tx];
        const float v1 = xb[(size_t)(2 * cp + 1) * 4096 + n0 + tx];
        uint32_t hp, lp; pack2(v0, v1, hp, lp);
        th[ty + k * 8][tx] = hp; tl[ty + k * 8][tx] = lp;
    }
    __syncthreads();
    #pragma unroll
    for (int k = 0; k < 4; k++) {
        const int n = n0 + ty + k * 8;
        const size_t o = ((size_t)b * 4096 + n) * 256 + cp0 + tx;
        xh[o] = th[tx][ty + k * 8];
        xl[o] = tl[tx][ty + k * 8];
    }
}

__global__ void prepack_w_k(const float* __restrict__ W, int sk, int sc, int Kt,
                            uint32_t* __restrict__ wh, uint32_t* __restrict__ wl, int total)
{
    const int idx = blockIdx.x * 256 + threadIdx.x;
    if (idx >= total) return;
    const int kp2 = Kt >> 1;
    const int co = idx / kp2, kp = idx - co * kp2;
    const float v0 = W[(size_t)(2 * kp) * sk + (size_t)co * sc];
    const float v1 = W[(size_t)(2 * kp + 1) * sk + (size_t)co * sc];
    uint32_t hp, lp; pack2(v0, v1, hp, lp);
    wh[idx] = hp; wl[idx] = lp;
}

__global__ void prepack_wc_k(const float* __restrict__ W,
                             uint32_t* __restrict__ wh, uint32_t* __restrict__ wl)
{
    const int idx = blockIdx.x * 256 + threadIdx.x;
    if (idx >= 256 * 1152) return;
    const int co = idx / 1152, kp = idx - co * 1152;
    const int t = kp >> 7, cp = kp & 127;
    const float v0 = W[(size_t)co * 2304 + (2 * cp) * 9 + t];
    const float v1 = W[(size_t)co * 2304 + (2 * cp + 1) * 9 + t];
    uint32_t hp, lp; pack2(v0, v1, hp, lp);
    wh[idx] = hp; wl[idx] = lp;
}

// ---------------------------------------------------------------------------
// Small GEMM for off/aw: A = packed b2 section (reconstruct fp32), B fp32 KxN.
// ---------------------------------------------------------------------------
__global__ void __launch_bounds__(256) gemm_small_k(
    const uint32_t* __restrict__ Ahi, const uint32_t* __restrict__ Alo,
    const float* __restrict__ B, const float* __restrict__ bias,
    float* __restrict__ C, int N, long sC)
{
    __shared__ float As[16][64];
    __shared__ float Bs[16][64];
    const int t = threadIdx.x;
    const int tx = t & 15, ty = t >> 4;
    const int m0 = blockIdx.y * 64;
    const int b = blockIdx.z;
    Ahi += (size_t)b * 4096 * 640;
    Alo += (size_t)b * 4096 * 640;
    C   += (size_t)b * sC;

    float acc[4][4] = {};
    for (int k0 = 0; k0 < 256; k0 += 16) {
        {
            const int m = t >> 2, kq = (t & 3) * 4;
            const size_t base = (size_t)(m0 + m) * 640 + 384 + ((k0 + kq) >> 1);
            const uint32_t h0 = Ahi[base], h1 = Ahi[base + 1];
            const uint32_t l0 = Alo[base], l1 = Alo[base + 1];
            As[kq + 0][m] = unpk_lo(h0) + unpk_lo(l0);
            As[kq + 1][m] = unpk_hi(h0) + unpk_hi(l0);
            As[kq + 2][m] = unpk_lo(h1) + unpk_lo(l1);
            As[kq + 3][m] = unpk_hi(h1) + unpk_hi(l1);
        }
        #pragma unroll
        for (int rr = 0; rr < 4; rr++) {
            const int i = t + 256 * rr;
            const int k = i >> 6, n = i & 63;
            Bs[k][n] = (n < N) ? B[(size_t)(k0 + k) * N + n] : 0.f;
        }
        __syncthreads();
        #pragma unroll
        for (int kk = 0; kk < 16; kk++) {
            float4 a = *(const float4*)&As[kk][ty * 4];
            float4 bb = *(const float4*)&Bs[kk][tx * 4];
            float av[4] = {a.x, a.y, a.z, a.w};
            float bv[4] = {bb.x, bb.y, bb.z, bb.w};
            #pragma unroll
            for (int i = 0; i < 4; i++)
                #pragma unroll
                for (int j = 0; j < 4; j++)
                    acc[i][j] += av[i] * bv[j];
        }
        __syncthreads();
    }
    #pragma unroll
    for (int i = 0; i < 4; i++) {
        const int m = m0 + ty * 4 + i;
        #pragma unroll
        for (int j = 0; j < 4; j++) {
            const int n = tx * 4 + j;
            if (n < N) C[(size_t)m * N + n] = acc[i][j] + bias[n];
        }
    }
}

// ---------------------------------------------------------------------------
// Deformable sampling -> packed hi/lo output
// ---------------------------------------------------------------------------
__global__ void __launch_bounds__(256) msda_sample_k(
    const float* __restrict__ value, const float* __restrict__ off,
    const float* __restrict__ awraw, const float* __restrict__ bbox,
    uint32_t* __restrict__ smpH, uint32_t* __restrict__ smpL)
{
    const int bl   = blockIdx.x;
    const int h    = threadIdx.x >> 5;
    const int lane = threadIdx.x & 31;
    const float* offp = off + (size_t)bl * 64 + h * 8;
    const float* awp  = awraw + (size_t)bl * 32 + h * 4;
    const float bx = bbox[(size_t)bl * 2 + 0];
    const float by = bbox[(size_t)bl * 2 + 1];

    float a0 = awp[0], a1 = awp[1], a2 = awp[2], a3 = awp[3];
    float mx = fmaxf(fmaxf(a0, a1), fmaxf(a2, a3));
    float e0 = __expf(a0 - mx), e1 = __expf(a1 - mx);
    float e2 = __expf(a2 - mx), e3 = __expf(a3 - mx);
    float inv = 1.f / (e0 + e1 + e2 + e3);
    float awv[4] = {e0 * inv, e1 * inv, e2 * inv, e3 * inv};

    const int b = bl >> 12;
    const float* vb = value + (size_t)b * HWN * 256 + h * 32 + lane;
    float acc = 0.f;
    #pragma unroll
    for (int p = 0; p < 4; p++) {
        float gx = (bx + offp[p * 2 + 0] * (1.f / 64.f)) * 64.f - 0.5f;
        float gy = (by + offp[p * 2 + 1] * (1.f / 64.f)) * 64.f - 0.5f;
        float x0f = floorf(gx), y0f = floorf(gy);
        float wx1 = gx - x0f, wy1 = gy - y0f;
        float wx0 = 1.f - wx1, wy0 = 1.f - wy1;
        int x0 = (int)x0f, y0 = (int)y0f;
        float s = 0.f;
        if ((unsigned)x0 < 64u && (unsigned)y0 < 64u)
            s += wx0 * wy0 * vb[(size_t)(y0 * 64 + x0) * 256];
        if ((unsigned)(x0 + 1) < 64u && (unsigned)y0 < 64u)
            s += wx1 * wy0 * vb[(size_t)(y0 * 64 + x0 + 1) * 256];
        if ((unsigned)x0 < 64u && (unsigned)(y0 + 1) < 64u)
            s += wx0 * wy1 * vb[(size_t)((y0 + 1) * 64 + x0) * 256];
        if ((unsigned)(x0 + 1) < 64u && (unsigned)(y0 + 1) < 64u)
            s += wx1 * wy1 * vb[(size_t)((y0 + 1) * 64 + x0 + 1) * 256];
        acc += awv[p] * s;
    }
    const float vOdd = __shfl_down_sync(0xffffffffu, acc, 1);
    if ((lane & 1) == 0) {
        uint32_t hp, lp; pack2(acc, vOdd, hp, lp);
        const size_t o = (size_t)bl * 128 + h * 16 + (lane >> 1);
        smpH[o] = hp; smpL[o] = lp;
    }
}

// ---------------------------------------------------------------------------
extern "C" void kernel_launch(void* const* d_in, const int* in_sizes, int n_in,
                              void* d_out, int out_size)
{
    const float* x       = (const float*)d_in[0];
    const float* bbox    = (const float*)d_in[1];
    const float* cv1_w   = (const float*)d_in[3];
    const float* mc[4]   = {(const float*)d_in[4], (const float*)d_in[5],
                            (const float*)d_in[6], (const float*)d_in[7]};
    const float* vproj_w = (const float*)d_in[8];
    const float* vproj_b = (const float*)d_in[9];
    const float* off_w   = (const float*)d_in[10];
    const float* off_b   = (const float*)d_in[11];
    const float* aw_w    = (const float*)d_in[12];
    const float* aw_b    = (const float*)d_in[13];
    const float* out_w   = (const float*)d_in[14];
    const float* out_b   = (const float*)d_in[15];
    const float* cv2_w   = (const float*)d_in[16];
    float* out = (float*)d_out;

    uint32_t *xp_h, *xp_l, *catp_h, *catp_l, *s0p_h, *s0p_l, *smpp_h, *smpp_l;
    uint32_t *wcv1_h, *wcv1_l, *wcv2_h, *wcv2_l, *wvp_h, *wvp_l, *wop_h, *wop_l;
    uint32_t *wc_h, *wc_l;
    float *val, *offb, *awb;
    cudaGetSymbolAddress((void**)&xp_h, g_xp_h);   cudaGetSymbolAddress((void**)&xp_l, g_xp_l);
    cudaGetSymbolAddress((void**)&catp_h, g_catp_h); cudaGetSymbolAddress((void**)&catp_l, g_catp_l);
    cudaGetSymbolAddress((void**)&s0p_h, g_s0p_h); cudaGetSymbolAddress((void**)&s0p_l, g_s0p_l);
    cudaGetSymbolAddress((void**)&smpp_h, g_smpp_h); cudaGetSymbolAddress((void**)&smpp_l, g_smpp_l);
    cudaGetSymbolAddress((void**)&wcv1_h, g_wcv1_h); cudaGetSymbolAddress((void**)&wcv1_l, g_wcv1_l);
    cudaGetSymbolAddress((void**)&wcv2_h, g_wcv2_h); cudaGetSymbolAddress((void**)&wcv2_l, g_wcv2_l);
    cudaGetSymbolAddress((void**)&wvp_h, g_wvp_h); cudaGetSymbolAddress((void**)&wvp_l, g_wvp_l);
    cudaGetSymbolAddress((void**)&wop_h, g_wop_h); cudaGetSymbolAddress((void**)&wop_l, g_wop_l);
    cudaGetSymbolAddress((void**)&wc_h, g_wc_h);   cudaGetSymbolAddress((void**)&wc_l, g_wc_l);
    cudaGetSymbolAddress((void**)&val, g_val);
    cudaGetSymbolAddress((void**)&offb, g_off);
    cudaGetSymbolAddress((void**)&awb, g_aw);

    // ---- prepack weights + input ----
    prepack_w_k<<<(512*256 + 255)/256, 256>>>(cv1_w, 1, 512, 512, wcv1_h, wcv1_l, 512*256);
    prepack_w_k<<<(512*640 + 255)/256, 256>>>(cv2_w, 1, 1280, 1280, wcv2_h, wcv2_l, 512*640);
    prepack_w_k<<<(256*128 + 255)/256, 256>>>(vproj_w, 256, 1, 256, wvp_h, wvp_l, 256*128);
    prepack_w_k<<<(256*128 + 255)/256, 256>>>(out_w, 256, 1, 256, wop_h, wop_l, 256*128);
    for (int i = 0; i < 4; i++)
        prepack_wc_k<<<(256*1152 + 255)/256, 256>>>(mc[i], wc_h + (size_t)i*256*1152,
                                                    wc_l + (size_t)i*256*1152);
    prepack_x_k<<<dim3(128, 8, NB), dim3(32, 8)>>>(x, xp_h, xp_l);

    // ---- cv1: 512 out-ch -> cat sections a|b (pairs 0..255), SiLU ----
    mm_hmma<false,0,true,false><<<dim3(32, 4, NB), 256>>>(
        xp_h, xp_l, 256, 0, wcv1_h, wcv1_l, 256, nullptr,
        nullptr, 0, 0, catp_h, catp_l, 640, 0, 512);

    // ---- bottleneck convs: b -> b1 -> b2 ----
    mm_hmma<true,0,true,false><<<dim3(32, 2, NB), 256>>>(
        catp_h, catp_l, 640, 128, wc_h + 0*256*1152, wc_l + 0*256*1152, 1152, nullptr,
        nullptr, 0, 0, s0p_h, s0p_l, 128, 0, 2304);
    mm_hmma<true,0,true,false><<<dim3(32, 2, NB), 256>>>(
        s0p_h, s0p_l, 128, 0, wc_h + 1*256*1152, wc_l + 1*256*1152, 1152, nullptr,
        nullptr, 0, 0, catp_h, catp_l, 640, 256, 2304);
    mm_hmma<true,0,true,false><<<dim3(32, 2, NB), 256>>>(
        catp_h, catp_l, 640, 256, wc_h + 2*256*1152, wc_l + 2*256*1152, 1152, nullptr,
        nullptr, 0, 0, s0p_h, s0p_l, 128, 0, 2304);
    mm_hmma<true,0,true,false><<<dim3(32, 2, NB), 256>>>(
        s0p_h, s0p_l, 128, 0, wc_h + 3*256*1152, wc_l + 3*256*1152, 1152, nullptr,
        nullptr, 0, 0, catp_h, catp_l, 640, 384, 2304);

    // ---- vproj: fp32 out (L,256) + bias ----
    mm_hmma<false,1,false,true><<<dim3(32, 2, NB), 256>>>(
        catp_h, catp_l, 640, 384, wvp_h, wvp_l, 128, vproj_b,
        val, 256, 4096L*256, nullptr, nullptr, 0, 0, 256);

    // ---- off / aw projections (fp32 small GEMM) ----
    gemm_small_k<<<dim3(1, 64, NB), 256>>>(catp_h, catp_l, off_w, off_b, offb, 64, 4096L*64);
    gemm_small_k<<<dim3(1, 64, NB), 256>>>(catp_h, catp_l, aw_w, aw_b, awb, 32, 4096L*32);

    // ---- deformable sampling -> packed smp ----
    msda_sample_k<<<NB * HWN, 256>>>(val, offb, awb, bbox, smpp_h, smpp_l);

    // ---- output projection -> cat attn section (pairs 512..639), bias ----
    mm_hmma<false,0,false,true><<<dim3(32, 2, NB), 256>>>(
        smpp_h, smpp_l, 128, 0, wop_h, wop_l, 128, out_b,
        nullptr, 0, 0, catp_h, catp_l, 640, 512, 256);

    // ---- cv2: K=1280 over full cat, SiLU, channel-major fp32 out ----
    mm_hmma<false,2,true,false><<<dim3(32, 4, NB), 256>>>(
        catp_h, catp_l, 640, 0, wcv2_h, wcv2_l, 640, nullptr,
        out, 4096, 512L*4096, nullptr, nullptr, 0, 0, 1280);
}

// round 6
// speedup vs baseline: 4.1052x; 1.7122x over previous
#include <cuda_runtime.h>
#include <cuda_bf16.h>
#include <cstdint>

// ---------------------------------------------------------------------------
// C2fDA via legacy HMMA (mma.sync m16n8k16 bf16), cp.async pipelined +
// ldmatrix fragments. Split-3 hi/lo bf16, fp32 accum (err ~1e-5).
// B=8, C1=512, C=256, D=256, NH=8, NP=4, NL=1, H=W=64, L=4096
// ---------------------------------------------------------------------------

#define NB 8
#define HWN 4096

// ---------------- scratch (allocation-guard-safe) --------------------------
__device__ uint32_t g_xp_h [(size_t)NB*4096*256];
__device__ uint32_t g_xp_l [(size_t)NB*4096*256];
__device__ uint32_t g_catp_h[(size_t)NB*4096*640];   // [a|b|b1|b2|attn] pairs
__device__ uint32_t g_catp_l[(size_t)NB*4096*640];
__device__ uint32_t g_s0p_h[(size_t)NB*4096*128];
__device__ uint32_t g_s0p_l[(size_t)NB*4096*128];
__device__ uint32_t g_smpp_h[(size_t)NB*4096*128];
__device__ uint32_t g_smpp_l[(size_t)NB*4096*128];
__device__ float    g_val  [(size_t)NB*4096*256];
__device__ float    g_off  [(size_t)NB*4096*64];
__device__ float    g_aw   [(size_t)NB*4096*32];
__device__ uint32_t g_wcv1_h[512*256],  g_wcv1_l[512*256];
__device__ uint32_t g_wcv2_h[512*640],  g_wcv2_l[512*640];
__device__ uint32_t g_wvp_h [256*128],  g_wvp_l [256*128];
__device__ uint32_t g_wop_h [256*128],  g_wop_l [256*128];
__device__ uint32_t g_wc_h  [4][256*1152], g_wc_l[4][256*1152];

__device__ __forceinline__ float silu_f(float x) { return x / (1.f + __expf(-x)); }

__device__ __forceinline__ void hilo16(float v, unsigned short& h, unsigned short& l) {
    __nv_bfloat16 hb = __float2bfloat16(v);
    float res = v - __bfloat162float(hb);
    __nv_bfloat16 lb = __float2bfloat16(res);
    h = __bfloat16_as_ushort(hb); l = __bfloat16_as_ushort(lb);
}
__device__ __forceinline__ void pack2(float v0, float v1, uint32_t& hp, uint32_t& lp) {
    unsigned short h0, l0, h1, l1;
    hilo16(v0, h0, l0); hilo16(v1, h1, l1);
    hp = ((uint32_t)h1 << 16) | h0;
    lp = ((uint32_t)l1 << 16) | l0;
}
__device__ __forceinline__ float unpk_lo(uint32_t u) {
    return __bfloat162float(__ushort_as_bfloat16((unsigned short)(u & 0xffff)));
}
__device__ __forceinline__ float unpk_hi(uint32_t u) {
    return __bfloat162float(__ushort_as_bfloat16((unsigned short)(u >> 16)));
}

__device__ __forceinline__ void mma16816(float* d, const uint32_t* a, const uint32_t* b) {
    asm volatile(
        "mma.sync.aligned.m16n8k16.row.col.f32.bf16.bf16.f32 "
        "{%0,%1,%2,%3}, {%4,%5,%6,%7}, {%8,%9}, {%0,%1,%2,%3};"
        : "+f"(d[0]), "+f"(d[1]), "+f"(d[2]), "+f"(d[3])
        : "r"(a[0]), "r"(a[1]), "r"(a[2]), "r"(a[3]), "r"(b[0]), "r"(b[1]));
}
__device__ __forceinline__ void ldsm4(uint32_t* r, uint32_t addr) {
    asm volatile("ldmatrix.sync.aligned.m8n8.x4.shared.b16 {%0,%1,%2,%3}, [%4];"
                 : "=r"(r[0]), "=r"(r[1]), "=r"(r[2]), "=r"(r[3]) : "r"(addr));
}
__device__ __forceinline__ uint32_t smem_u32(const void* p) {
    uint32_t a;
    asm("{ .reg .u64 t; cvta.to.shared.u64 t, %1; cvt.u32.u64 %0, t; }"
        : "=r"(a) : "l"(p));
    return a;
}
__device__ __forceinline__ void cpa16(uint32_t dst, const void* src, int srcsize) {
    asm volatile("cp.async.cg.shared.global [%0], [%1], 16, %2;"
                 :: "r"(dst), "l"(src), "r"(srcsize) : "memory");
}
#define CP_COMMIT() asm volatile("cp.async.commit_group;" ::: "memory")
#define CP_WAIT1()  asm volatile("cp.async.wait_group 1;" ::: "memory")
#define CP_WAIT0()  asm volatile("cp.async.wait_group 0;" ::: "memory")

// ---------------------------------------------------------------------------
// Pipelined HMMA matmul: D[128 spatial][128 out-ch] per CTA, K-chunk 32.
// Smem tiles row-major [row][16 u32], row stride 20 u32 (80B) -> ldmatrix
// conflict-free. 2-stage cp.async double buffer.
// Stage layout: Ah | Al | Bh | Bl, each 128*20*4 = 10240 B. Stage = 40960 B.
// ---------------------------------------------------------------------------
#define TILE_B 10240
#define STAGE_B 40960

template<bool CONV, int OUTM, bool SILU, bool BIASF>
__global__ void __launch_bounds__(256, 2) mm_hmma(
    const uint32_t* __restrict__ Ahi, const uint32_t* __restrict__ Alo,
    int ldap, int apbase,
    const uint32_t* __restrict__ Bhi, const uint32_t* __restrict__ Blo, int ldbp,
    const float* __restrict__ bias,
    float* __restrict__ outF, int ldoutF, long outFb,
    uint32_t* __restrict__ Ohi, uint32_t* __restrict__ Olo, int ldop, int opbase,
    int Ktot)
{
    extern __shared__ char smem[];
    const uint32_t sbase = smem_u32(smem);

    const int tid  = threadIdx.x;
    const int lane = tid & 31;
    const int wid  = tid >> 5;
    const int g    = lane >> 2;
    const int t4   = lane & 3;
    const int m0w  = (wid & 1) * 64;
    const int n0w  = (wid >> 1) * 32;
    const int n0 = blockIdx.x * 128, c0 = blockIdx.y * 128, b = blockIdx.z;

    Ahi += (size_t)b * 4096 * ldap;
    Alo += (size_t)b * 4096 * ldap;
    if (OUTM == 0) { Ohi += (size_t)b * 4096 * ldop; Olo += (size_t)b * 4096 * ldop; }
    else           { outF += (size_t)b * outFb; }

    // ldmatrix lane roles
    const int rit = lane & 7, sel = lane >> 3;
    // A: matrices 0:(m0-7,k0-7) 1:(m8-15,k0-7) 2:(m0-7,k8-15) 3:(m8-15,k8-15)
    const uint32_t aFragBase = (uint32_t)((m0w + (sel & 1) * 8 + rit) * 80 + (sel >> 1) * 16);
    // B x4 covers nf pair: 0:(nfA,k0-7) 1:(nfA,k8-15) 2:(nfB,k0-7) 3:(nfB,k8-15)
    const uint32_t bFragBase = (uint32_t)((n0w + (sel >> 1) * 8 + rit) * 80 + (sel & 1) * 16);

    float acc[4][4][4] = {};
    const int NC = Ktot >> 5;

    // ---- loader lambda-ish macro: issue cp.async for chunk ch into stage st
    auto load_chunk = [&](int ch, int st) {
        const uint32_t stAh = sbase + st * STAGE_B;
        const uint32_t stAl = stAh + TILE_B;
        const uint32_t stBh = stAh + 2 * TILE_B;
        const uint32_t stBl = stAh + 3 * TILE_B;
        int cp0;
        int t9 = 0, dy = 0, dx = 0;
        if (CONV) { t9 = ch >> 3; dy = t9 / 3; dx = t9 - dy * 3; cp0 = (ch & 7) * 16; }
        else      { cp0 = ch * 16; }
        #pragma unroll
        for (int r = 0; r < 2; r++) {
            const int idx = tid + 256 * r;          // 0..511
            const int row = idx >> 2, q = idx & 3;
            // A
            int srcRow = n0 + row;
            int vsz = 16;
            if (CONV) {
                const int nn = n0 + row;
                const int yy = (nn >> 6) + dy - 1, xx = (nn & 63) + dx - 1;
                if (((unsigned)yy >= 64u) || ((unsigned)xx >= 64u)) vsz = 0;
                srcRow = yy * 64 + xx;
            }
            const size_t aoff = (size_t)srcRow * ldap + apbase + cp0 + q * 4;
            cpa16(stAh + row * 80 + q * 16, Ahi + aoff, vsz);
            cpa16(stAl + row * 80 + q * 16, Alo + aoff, vsz);
            // B (weights, always valid)
            const size_t boff = (size_t)(c0 + row) * ldbp + ch * 16 + q * 4;
            cpa16(stBh + row * 80 + q * 16, Bhi + boff, 16);
            cpa16(stBl + row * 80 + q * 16, Blo + boff, 16);
        }
    };

    load_chunk(0, 0);
    CP_COMMIT();

    for (int ch = 0; ch < NC; ch++) {
        const int st = ch & 1;
        if (ch + 1 < NC) { load_chunk(ch + 1, st ^ 1); CP_COMMIT(); CP_WAIT1(); }
        else             { CP_WAIT0(); }
        __syncthreads();

        const uint32_t stAh = sbase + st * STAGE_B;
        const uint32_t stAl = stAh + TILE_B;
        const uint32_t stBh = stAh + 2 * TILE_B;
        const uint32_t stBl = stAh + 3 * TILE_B;

        #pragma unroll
        for (int ks = 0; ks < 2; ks++) {
            const uint32_t ko = ks * 32;
            uint32_t a[4][4], bhf[4][2], blf[4][2];
            #pragma unroll
            for (int mf = 0; mf < 4; mf++)
                ldsm4(a[mf], stAh + aFragBase + mf * (16 * 80) + ko);
            #pragma unroll
            for (int nfp = 0; nfp < 2; nfp++) {
                uint32_t rb[4];
                ldsm4(rb, stBh + bFragBase + nfp * (16 * 80) + ko);
                bhf[2 * nfp][0] = rb[0]; bhf[2 * nfp][1] = rb[1];
                bhf[2 * nfp + 1][0] = rb[2]; bhf[2 * nfp + 1][1] = rb[3];
                ldsm4(rb, stBl + bFragBase + nfp * (16 * 80) + ko);
                blf[2 * nfp][0] = rb[0]; blf[2 * nfp][1] = rb[1];
                blf[2 * nfp + 1][0] = rb[2]; blf[2 * nfp + 1][1] = rb[3];
            }
            #pragma unroll
            for (int mf = 0; mf < 4; mf++)
                #pragma unroll
                for (int nf = 0; nf < 4; nf++) {
                    mma16816(acc[mf][nf], a[mf], bhf[nf]);
                    mma16816(acc[mf][nf], a[mf], blf[nf]);
                }
            #pragma unroll
            for (int mf = 0; mf < 4; mf++)
                ldsm4(a[mf], stAl + aFragBase + mf * (16 * 80) + ko);
            #pragma unroll
            for (int mf = 0; mf < 4; mf++)
                #pragma unroll
                for (int nf = 0; nf < 4; nf++)
                    mma16816(acc[mf][nf], a[mf], bhf[nf]);
        }
        __syncthreads();
    }

    // ---- epilogue ----
    #pragma unroll
    for (int mf = 0; mf < 4; mf++) {
        const int r0 = n0 + m0w + mf * 16 + g;
        #pragma unroll
        for (int nf = 0; nf < 4; nf++) {
            const int ncol = c0 + n0w + nf * 8 + t4 * 2;
            float v00 = acc[mf][nf][0], v01 = acc[mf][nf][1];
            float v10 = acc[mf][nf][2], v11 = acc[mf][nf][3];
            if (BIASF) {
                const float b0f = bias[ncol], b1f = bias[ncol + 1];
                v00 += b0f; v01 += b1f; v10 += b0f; v11 += b1f;
            }
            if (SILU) {
                v00 = silu_f(v00); v01 = silu_f(v01);
                v10 = silu_f(v10); v11 = silu_f(v11);
            }
            if (OUTM == 0) {
                uint32_t hp, lp;
                pack2(v00, v01, hp, lp);
                const size_t i0 = (size_t)r0 * ldop + opbase + (ncol >> 1);
                Ohi[i0] = hp; Olo[i0] = lp;
                pack2(v10, v11, hp, lp);
                const size_t i1 = (size_t)(r0 + 8) * ldop + opbase + (ncol >> 1);
                Ohi[i1] = hp; Olo[i1] = lp;
            } else if (OUTM == 1) {
                *(float2*)(outF + (size_t)r0 * ldoutF + ncol)       = make_float2(v00, v01);
                *(float2*)(outF + (size_t)(r0 + 8) * ldoutF + ncol) = make_float2(v10, v11);
            } else {
                outF[(size_t)ncol       * ldoutF + r0]     = v00;
                outF[(size_t)(ncol + 1) * ldoutF + r0]     = v01;
                outF[(size_t)ncol       * ldoutF + r0 + 8] = v10;
                outF[(size_t)(ncol + 1) * ldoutF + r0 + 8] = v11;
            }
        }
    }
}

// ---------------------------------------------------------------------------
// Prepack kernels
// ---------------------------------------------------------------------------
__global__ void prepack_x_k(const float* __restrict__ x,
                            uint32_t* __restrict__ xh, uint32_t* __restrict__ xl)
{
    __shared__ uint32_t th[32][33], tl[32][33];
    const int tx = threadIdx.x, ty = threadIdx.y;
    const int n0 = blockIdx.x * 32, cp0 = blockIdx.y * 32, b = blockIdx.z;
    const float* xb = x + (size_t)b * 512 * 4096;
    #pragma unroll
    for (int k = 0; k < 4; k++) {
        const int cp = cp0 + ty + k * 8;
        const float v0 = xb[(size_t)(2 * cp) * 4096 + n0 + tx];
        const float v1 = xb[(size_t)(2 * cp + 1) * 4096 + n0 + tx];
        uint32_t hp, lp; pack2(v0, v1, hp, lp);
        th[ty + k * 8][tx] = hp; tl[ty + k * 8][tx] = lp;
    }
    __syncthreads();
    #pragma unroll
    for (int k = 0; k < 4; k++) {
        const int n = n0 + ty + k * 8;
        const size_t o = ((size_t)b * 4096 + n) * 256 + cp0 + tx;
        xh[o] = th[tx][ty + k * 8];
        xl[o] = tl[tx][ty + k * 8];
    }
}

__global__ void prepack_w_k(const float* __restrict__ W, int sk, int sc, int Kt,
                            uint32_t* __restrict__ wh, uint32_t* __restrict__ wl, int total)
{
    const int idx = blockIdx.x * 256 + threadIdx.x;
    if (idx >= total) return;
    const int kp2 = Kt >> 1;
    const int co = idx / kp2, kp = idx - co * kp2;
    const float v0 = W[(size_t)(2 * kp) * sk + (size_t)co * sc];
    const float v1 = W[(size_t)(2 * kp + 1) * sk + (size_t)co * sc];
    uint32_t hp, lp; pack2(v0, v1, hp, lp);
    wh[idx] = hp; wl[idx] = lp;
}

__global__ void prepack_wc_k(const float* __restrict__ W,
                             uint32_t* __restrict__ wh, uint32_t* __restrict__ wl)
{
    const int idx = blockIdx.x * 256 + threadIdx.x;
    if (idx >= 256 * 1152) return;
    const int co = idx / 1152, kp = idx - co * 1152;
    const int t = kp >> 7, cp = kp & 127;
    const float v0 = W[(size_t)co * 2304 + (2 * cp) * 9 + t];
    const float v1 = W[(size_t)co * 2304 + (2 * cp + 1) * 9 + t];
    uint32_t hp, lp; pack2(v0, v1, hp, lp);
    wh[idx] = hp; wl[idx] = lp;
}

// ---------------------------------------------------------------------------
// Small GEMM for off/aw: A = packed b2 section (reconstruct fp32), B fp32 KxN.
// ---------------------------------------------------------------------------
__global__ void __launch_bounds__(256) gemm_small_k(
    const uint32_t* __restrict__ Ahi, const uint32_t* __restrict__ Alo,
    const float* __restrict__ B, const float* __restrict__ bias,
    float* __restrict__ C, int N, long sC)
{
    __shared__ float As[16][64];
    __shared__ float Bs[16][64];
    const int t = threadIdx.x;
    const int tx = t & 15, ty = t >> 4;
    const int m0 = blockIdx.y * 64;
    const int b = blockIdx.z;
    Ahi += (size_t)b * 4096 * 640;
    Alo += (size_t)b * 4096 * 640;
    C   += (size_t)b * sC;

    float acc[4][4] = {};
    for (int k0 = 0; k0 < 256; k0 += 16) {
        {
            const int m = t >> 2, kq = (t & 3) * 4;
            const size_t base = (size_t)(m0 + m) * 640 + 384 + ((k0 + kq) >> 1);
            const uint32_t h0 = Ahi[base], h1 = Ahi[base + 1];
            const uint32_t l0 = Alo[base], l1 = Alo[base + 1];
            As[kq + 0][m] = unpk_lo(h0) + unpk_lo(l0);
            As[kq + 1][m] = unpk_hi(h0) + unpk_hi(l0);
            As[kq + 2][m] = unpk_lo(h1) + unpk_lo(l1);
            As[kq + 3][m] = unpk_hi(h1) + unpk_hi(l1);
        }
        #pragma unroll
        for (int rr = 0; rr < 4; rr++) {
            const int i = t + 256 * rr;
            const int k = i >> 6, n = i & 63;
            Bs[k][n] = (n < N) ? B[(size_t)(k0 + k) * N + n] : 0.f;
        }
        __syncthreads();
        #pragma unroll
        for (int kk = 0; kk < 16; kk++) {
            float4 a = *(const float4*)&As[kk][ty * 4];
            float4 bb = *(const float4*)&Bs[kk][tx * 4];
            float av[4] = {a.x, a.y, a.z, a.w};
            float bv[4] = {bb.x, bb.y, bb.z, bb.w};
            #pragma unroll
            for (int i = 0; i < 4; i++)
                #pragma unroll
                for (int j = 0; j < 4; j++)
                    acc[i][j] += av[i] * bv[j];
        }
        __syncthreads();
    }
    #pragma unroll
    for (int i = 0; i < 4; i++) {
        const int m = m0 + ty * 4 + i;
        #pragma unroll
        for (int j = 0; j < 4; j++) {
            const int n = tx * 4 + j;
            if (n < N) C[(size_t)m * N + n] = acc[i][j] + bias[n];
        }
    }
}

// ---------------------------------------------------------------------------
// Deformable sampling -> packed hi/lo output
// ---------------------------------------------------------------------------
__global__ void __launch_bounds__(256) msda_sample_k(
    const float* __restrict__ value, const float* __restrict__ off,
    const float* __restrict__ awraw, const float* __restrict__ bbox,
    uint32_t* __restrict__ smpH, uint32_t* __restrict__ smpL)
{
    const int bl   = blockIdx.x;
    const int h    = threadIdx.x >> 5;
    const int lane = threadIdx.x & 31;
    const float* offp = off + (size_t)bl * 64 + h * 8;
    const float* awp  = awraw + (size_t)bl * 32 + h * 4;
    const float bx = bbox[(size_t)bl * 2 + 0];
    const float by = bbox[(size_t)bl * 2 + 1];

    float a0 = awp[0], a1 = awp[1], a2 = awp[2], a3 = awp[3];
    float mx = fmaxf(fmaxf(a0, a1), fmaxf(a2, a3));
    float e0 = __expf(a0 - mx), e1 = __expf(a1 - mx);
    float e2 = __expf(a2 - mx), e3 = __expf(a3 - mx);
    float inv = 1.f / (e0 + e1 + e2 + e3);
    float awv[4] = {e0 * inv, e1 * inv, e2 * inv, e3 * inv};

    const int b = bl >> 12;
    const float* vb = value + (size_t)b * HWN * 256 + h * 32 + lane;
    float acc = 0.f;
    #pragma unroll
    for (int p = 0; p < 4; p++) {
        float gx = (bx + offp[p * 2 + 0] * (1.f / 64.f)) * 64.f - 0.5f;
        float gy = (by + offp[p * 2 + 1] * (1.f / 64.f)) * 64.f - 0.5f;
        float x0f = floorf(gx), y0f = floorf(gy);
        float wx1 = gx - x0f, wy1 = gy - y0f;
        float wx0 = 1.f - wx1, wy0 = 1.f - wy1;
        int x0 = (int)x0f, y0 = (int)y0f;
        float s = 0.f;
        if ((unsigned)x0 < 64u && (unsigned)y0 < 64u)
            s += wx0 * wy0 * vb[(size_t)(y0 * 64 + x0) * 256];
        if ((unsigned)(x0 + 1) < 64u && (unsigned)y0 < 64u)
            s += wx1 * wy0 * vb[(size_t)(y0 * 64 + x0 + 1) * 256];
        if ((unsigned)x0 < 64u && (unsigned)(y0 + 1) < 64u)
            s += wx0 * wy1 * vb[(size_t)((y0 + 1) * 64 + x0) * 256];
        if ((unsigned)(x0 + 1) < 64u && (unsigned)(y0 + 1) < 64u)
            s += wx1 * wy1 * vb[(size_t)((y0 + 1) * 64 + x0 + 1) * 256];
        acc += awv[p] * s;
    }
    const float vOdd = __shfl_down_sync(0xffffffffu, acc, 1);
    if ((lane & 1) == 0) {
        uint32_t hp, lp; pack2(acc, vOdd, hp, lp);
        const size_t o = (size_t)bl * 128 + h * 16 + (lane >> 1);
        smpH[o] = hp; smpL[o] = lp;
    }
}

// ---------------------------------------------------------------------------
extern "C" void kernel_launch(void* const* d_in, const int* in_sizes, int n_in,
                              void* d_out, int out_size)
{
    const float* x       = (const float*)d_in[0];
    const float* bbox    = (const float*)d_in[1];
    const float* cv1_w   = (const float*)d_in[3];
    const float* mc[4]   = {(const float*)d_in[4], (const float*)d_in[5],
                            (const float*)d_in[6], (const float*)d_in[7]};
    const float* vproj_w = (const float*)d_in[8];
    const float* vproj_b = (const float*)d_in[9];
    const float* off_w   = (const float*)d_in[10];
    const float* off_b   = (const float*)d_in[11];
    const float* aw_w    = (const float*)d_in[12];
    const float* aw_b    = (const float*)d_in[13];
    const float* out_w   = (const float*)d_in[14];
    const float* out_b   = (const float*)d_in[15];
    const float* cv2_w   = (const float*)d_in[16];
    float* out = (float*)d_out;

    uint32_t *xp_h, *xp_l, *catp_h, *catp_l, *s0p_h, *s0p_l, *smpp_h, *smpp_l;
    uint32_t *wcv1_h, *wcv1_l, *wcv2_h, *wcv2_l, *wvp_h, *wvp_l, *wop_h, *wop_l;
    uint32_t *wc_h, *wc_l;
    float *val, *offb, *awb;
    cudaGetSymbolAddress((void**)&xp_h, g_xp_h);   cudaGetSymbolAddress((void**)&xp_l, g_xp_l);
    cudaGetSymbolAddress((void**)&catp_h, g_catp_h); cudaGetSymbolAddress((void**)&catp_l, g_catp_l);
    cudaGetSymbolAddress((void**)&s0p_h, g_s0p_h); cudaGetSymbolAddress((void**)&s0p_l, g_s0p_l);
    cudaGetSymbolAddress((void**)&smpp_h, g_smpp_h); cudaGetSymbolAddress((void**)&smpp_l, g_smpp_l);
    cudaGetSymbolAddress((void**)&wcv1_h, g_wcv1_h); cudaGetSymbolAddress((void**)&wcv1_l, g_wcv1_l);
    cudaGetSymbolAddress((void**)&wcv2_h, g_wcv2_h); cudaGetSymbolAddress((void**)&wcv2_l, g_wcv2_l);
    cudaGetSymbolAddress((void**)&wvp_h, g_wvp_h); cudaGetSymbolAddress((void**)&wvp_l, g_wvp_l);
    cudaGetSymbolAddress((void**)&wop_h, g_wop_h); cudaGetSymbolAddress((void**)&wop_l, g_wop_l);
    cudaGetSymbolAddress((void**)&wc_h, g_wc_h);   cudaGetSymbolAddress((void**)&wc_l, g_wc_l);
    cudaGetSymbolAddress((void**)&val, g_val);
    cudaGetSymbolAddress((void**)&offb, g_off);
    cudaGetSymbolAddress((void**)&awb, g_aw);

    const int DYN = 2 * STAGE_B;   // 81920
    cudaFuncSetAttribute(mm_hmma<false,0,true ,false>, cudaFuncAttributeMaxDynamicSharedMemorySize, DYN);
    cudaFuncSetAttribute(mm_hmma<true ,0,true ,false>, cudaFuncAttributeMaxDynamicSharedMemorySize, DYN);
    cudaFuncSetAttribute(mm_hmma<false,1,false,true >, cudaFuncAttributeMaxDynamicSharedMemorySize, DYN);
    cudaFuncSetAttribute(mm_hmma<false,0,false,true >, cudaFuncAttributeMaxDynamicSharedMemorySize, DYN);
    cudaFuncSetAttribute(mm_hmma<false,2,true ,false>, cudaFuncAttributeMaxDynamicSharedMemorySize, DYN);

    // ---- prepack weights + input ----
    prepack_w_k<<<(512*256 + 255)/256, 256>>>(cv1_w, 1, 512, 512, wcv1_h, wcv1_l, 512*256);
    prepack_w_k<<<(512*640 + 255)/256, 256>>>(cv2_w, 1, 1280, 1280, wcv2_h, wcv2_l, 512*640);
    prepack_w_k<<<(256*128 + 255)/256, 256>>>(vproj_w, 256, 1, 256, wvp_h, wvp_l, 256*128);
    prepack_w_k<<<(256*128 + 255)/256, 256>>>(out_w, 256, 1, 256, wop_h, wop_l, 256*128);
    for (int i = 0; i < 4; i++)
        prepack_wc_k<<<(256*1152 + 255)/256, 256>>>(mc[i], wc_h + (size_t)i*256*1152,
                                                    wc_l + (size_t)i*256*1152);
    prepack_x_k<<<dim3(128, 8, NB), dim3(32, 8)>>>(x, xp_h, xp_l);

    // ---- cv1: 512 out-ch -> cat sections a|b (pairs 0..255), SiLU ----
    mm_hmma<false,0,true,false><<<dim3(32, 4, NB), 256, DYN>>>(
        xp_h, xp_l, 256, 0, wcv1_h, wcv1_l, 256, nullptr,
        nullptr, 0, 0, catp_h, catp_l, 640, 0, 512);

    // ---- bottleneck convs: b -> b1 -> b2 ----
    mm_hmma<true,0,true,false><<<dim3(32, 2, NB), 256, DYN>>>(
        catp_h, catp_l, 640, 128, wc_h + 0*256*1152, wc_l + 0*256*1152, 1152, nullptr,
        nullptr, 0, 0, s0p_h, s0p_l, 128, 0, 2304);
    mm_hmma<true,0,true,false><<<dim3(32, 2, NB), 256, DYN>>>(
        s0p_h, s0p_l, 128, 0, wc_h + 1*256*1152, wc_l + 1*256*1152, 1152, nullptr,
        nullptr, 0, 0, catp_h, catp_l, 640, 256, 2304);
    mm_hmma<true,0,true,false><<<dim3(32, 2, NB), 256, DYN>>>(
        catp_h, catp_l, 640, 256, wc_h + 2*256*1152, wc_l + 2*256*1152, 1152, nullptr,
        nullptr, 0, 0, s0p_h, s0p_l, 128, 0, 2304);
    mm_hmma<true,0,true,false><<<dim3(32, 2, NB), 256, DYN>>>(
        s0p_h, s0p_l, 128, 0, wc_h + 3*256*1152, wc_l + 3*256*1152, 1152, nullptr,
        nullptr, 0, 0, catp_h, catp_l, 640, 384, 2304);

    // ---- vproj: fp32 out (L,256) + bias ----
    mm_hmma<false,1,false,true><<<dim3(32, 2, NB), 256, DYN>>>(
        catp_h, catp_l, 640, 384, wvp_h, wvp_l, 128, vproj_b,
        val, 256, 4096L*256, nullptr, nullptr, 0, 0, 256);

    // ---- off / aw projections (fp32 small GEMM) ----
    gemm_small_k<<<dim3(1, 64, NB), 256>>>(catp_h, catp_l, off_w, off_b, offb, 64, 4096L*64);
    gemm_small_k<<<dim3(1, 64, NB), 256>>>(catp_h, catp_l, aw_w, aw_b, awb, 32, 4096L*32);

    // ---- deformable sampling -> packed smp ----
    msda_sample_k<<<NB * HWN, 256>>>(val, offb, awb, bbox, smpp_h, smpp_l);

    // ---- output projection -> cat attn section (pairs 512..639), bias ----
    mm_hmma<false,0,false,true><<<dim3(32, 2, NB), 256, DYN>>>(
        smpp_h, smpp_l, 128, 0, wop_h, wop_l, 128, out_b,
        nullptr, 0, 0, catp_h, catp_l, 640, 512, 256);

    // ---- cv2: K=1280 over full cat, SiLU, channel-major fp32 out ----
    mm_hmma<false,2,true,false><<<dim3(32, 4, NB), 256, DYN>>>(
        catp_h, catp_l, 640, 0, wcv2_h, wcv2_l, 640, nullptr,
        out, 4096, 512L*4096, nullptr, nullptr, 0, 0, 1280);
}

// round 8
// speedup vs baseline: 4.2442x; 1.0339x over previous
#include <cuda_runtime.h>
#include <cuda_bf16.h>
#include <cstdint>

// ---------------------------------------------------------------------------
// C2fDA via legacy HMMA (mma.sync m16n8k16 bf16), cp.async pipelined +
// ldmatrix fragments. Split-3 hi/lo bf16, fp32 accum (err ~1e-5).
// B=8, C1=512, C=256, D=256, NH=8, NP=4, NL=1, H=W=64, L=4096
// ---------------------------------------------------------------------------

#define NB 8
#define HWN 4096

// ---------------- scratch (allocation-guard-safe) --------------------------
__device__ uint32_t g_xp_h [(size_t)NB*4096*256];
__device__ uint32_t g_xp_l [(size_t)NB*4096*256];
__device__ uint32_t g_catp_h[(size_t)NB*4096*640];   // [a|b|b1|b2|attn] pairs
__device__ uint32_t g_catp_l[(size_t)NB*4096*640];
__device__ uint32_t g_s0p_h[(size_t)NB*4096*128];
__device__ uint32_t g_s0p_l[(size_t)NB*4096*128];
__device__ uint32_t g_smpp_h[(size_t)NB*4096*128];
__device__ uint32_t g_smpp_l[(size_t)NB*4096*128];
__device__ float    g_pj   [(size_t)NB*4096*384];    // [val 256 | off 64 | aw 32 | pad 32]
__device__ uint32_t g_wcv1_h[512*256],  g_wcv1_l[512*256];
__device__ uint32_t g_wcv2_h[512*640],  g_wcv2_l[512*640];
__device__ uint32_t g_wpj_h [384*128],  g_wpj_l [384*128];
__device__ uint32_t g_wop_h [256*128],  g_wop_l [256*128];
__device__ uint32_t g_wc_h  [4*256*1152], g_wc_l[4*256*1152];
__device__ float    g_biasc [384];

__device__ __forceinline__ float silu_f(float x) { return x / (1.f + __expf(-x)); }

__device__ __forceinline__ void hilo16(float v, unsigned short& h, unsigned short& l) {
    __nv_bfloat16 hb = __float2bfloat16(v);
    float res = v - __bfloat162float(hb);
    __nv_bfloat16 lb = __float2bfloat16(res);
    h = __bfloat16_as_ushort(hb); l = __bfloat16_as_ushort(lb);
}
__device__ __forceinline__ void pack2(float v0, float v1, uint32_t& hp, uint32_t& lp) {
    unsigned short h0, l0, h1, l1;
    hilo16(v0, h0, l0); hilo16(v1, h1, l1);
    hp = ((uint32_t)h1 << 16) | h0;
    lp = ((uint32_t)l1 << 16) | l0;
}

__device__ __forceinline__ void mma16816(float* d, const uint32_t* a, const uint32_t* b) {
    asm volatile(
        "mma.sync.aligned.m16n8k16.row.col.f32.bf16.bf16.f32 "
        "{%0,%1,%2,%3}, {%4,%5,%6,%7}, {%8,%9}, {%0,%1,%2,%3};"
        : "+f"(d[0]), "+f"(d[1]), "+f"(d[2]), "+f"(d[3])
        : "r"(a[0]), "r"(a[1]), "r"(a[2]), "r"(a[3]), "r"(b[0]), "r"(b[1]));
}
__device__ __forceinline__ void ldsm4(uint32_t* r, uint32_t addr) {
    asm volatile("ldmatrix.sync.aligned.m8n8.x4.shared.b16 {%0,%1,%2,%3}, [%4];"
                 : "=r"(r[0]), "=r"(r[1]), "=r"(r[2]), "=r"(r[3]) : "r"(addr));
}
__device__ __forceinline__ uint32_t smem_u32(const void* p) {
    uint32_t a;
    asm("{ .reg .u64 t; cvta.to.shared.u64 t, %1; cvt.u32.u64 %0, t; }"
        : "=r"(a) : "l"(p));
    return a;
}
__device__ __forceinline__ void cpa16(uint32_t dst, const void* src, int srcsize) {
    asm volatile("cp.async.cg.shared.global [%0], [%1], 16, %2;"
                 :: "r"(dst), "l"(src), "r"(srcsize) : "memory");
}
#define CP_COMMIT() asm volatile("cp.async.commit_group;" ::: "memory")
#define CP_WAIT1()  asm volatile("cp.async.wait_group 1;" ::: "memory")
#define CP_WAIT0()  asm volatile("cp.async.wait_group 0;" ::: "memory")

// ---------------------------------------------------------------------------
// Pipelined HMMA matmul: D[128 spatial][128 out-ch] per CTA, K-chunk 32.
// Smem tiles [row][16 u32] stride 20 u32 (80B) -> ldmatrix conflict-free.
// 2-stage cp.async double buffer. Stage: Ah|Al|Bh|Bl x 10240B = 40960B.
// OUTM: 0 packed hi/lo [n][cpair]; 1 fp32 [n][ldoutF]; 2 fp32 [c][ldoutF]
//       (smem-staged transpose for coalesced stores).
// ---------------------------------------------------------------------------
#define TILE_B 10240
#define STAGE_B 40960

template<bool CONV, int OUTM, bool SILU, bool BIASF>
__global__ void __launch_bounds__(256, 2) mm_hmma(
    const uint32_t* __restrict__ Ahi, const uint32_t* __restrict__ Alo,
    int ldap, int apbase,
    const uint32_t* __restrict__ Bhi, const uint32_t* __restrict__ Blo, int ldbp,
    const float* __restrict__ bias,
    float* __restrict__ outF, int ldoutF, long outFb,
    uint32_t* __restrict__ Ohi, uint32_t* __restrict__ Olo, int ldop, int opbase,
    int Ktot)
{
    extern __shared__ char smem[];
    const uint32_t sbase = smem_u32(smem);

    const int tid  = threadIdx.x;
    const int lane = tid & 31;
    const int wid  = tid >> 5;
    const int g    = lane >> 2;
    const int t4   = lane & 3;
    const int m0w  = (wid & 1) * 64;
    const int n0w  = (wid >> 1) * 32;
    const int n0 = blockIdx.x * 128, c0 = blockIdx.y * 128, b = blockIdx.z;

    Ahi += (size_t)b * 4096 * ldap;
    Alo += (size_t)b * 4096 * ldap;

    const int rit = lane & 7, sel = lane >> 3;
    const uint32_t aFragBase = (uint32_t)((m0w + (sel & 1) * 8 + rit) * 80 + (sel >> 1) * 16);
    const uint32_t bFragBase = (uint32_t)((n0w + (sel >> 1) * 8 + rit) * 80 + (sel & 1) * 16);

    float acc[4][4][4] = {};
    const int NC = Ktot >> 5;

    auto load_chunk = [&](int ch, int st) {
        const uint32_t stAh = sbase + st * STAGE_B;
        const uint32_t stAl = stAh + TILE_B;
        const uint32_t stBh = stAh + 2 * TILE_B;
        const uint32_t stBl = stAh + 3 * TILE_B;
        int cp0;
        int dy = 0, dx = 0;
        if (CONV) { int t9 = ch >> 3; dy = t9 / 3; dx = t9 - dy * 3; cp0 = (ch & 7) * 16; }
        else      { cp0 = ch * 16; }
        #pragma unroll
        for (int r = 0; r < 2; r++) {
            const int idx = tid + 256 * r;
            const int row = idx >> 2, q = idx & 3;
            int srcRow = n0 + row;
            int vsz = 16;
            if (CONV) {
                const int nn = n0 + row;
                const int yy = (nn >> 6) + dy - 1, xx = (nn & 63) + dx - 1;
                if (((unsigned)yy >= 64u) || ((unsigned)xx >= 64u)) vsz = 0;
                srcRow = yy * 64 + xx;
            }
            const size_t aoff = (size_t)srcRow * ldap + apbase + cp0 + q * 4;
            cpa16(stAh + row * 80 + q * 16, Ahi + aoff, vsz);
            cpa16(stAl + row * 80 + q * 16, Alo + aoff, vsz);
            const size_t boff = (size_t)(c0 + row) * ldbp + ch * 16 + q * 4;
            cpa16(stBh + row * 80 + q * 16, Bhi + boff, 16);
            cpa16(stBl + row * 80 + q * 16, Blo + boff, 16);
        }
    };

    load_chunk(0, 0);
    CP_COMMIT();

    for (int ch = 0; ch < NC; ch++) {
        const int st = ch & 1;
        if (ch + 1 < NC) { load_chunk(ch + 1, st ^ 1); CP_COMMIT(); CP_WAIT1(); }
        else             { CP_WAIT0(); }
        __syncthreads();

        const uint32_t stAh = sbase + st * STAGE_B;
        const uint32_t stAl = stAh + TILE_B;
        const uint32_t stBh = stAh + 2 * TILE_B;
        const uint32_t stBl = stAh + 3 * TILE_B;

        #pragma unroll
        for (int ks = 0; ks < 2; ks++) {
            const uint32_t ko = ks * 32;
            uint32_t a[4][4];
            #pragma unroll
            for (int mf = 0; mf < 4; mf++)
                ldsm4(a[mf], stAh + aFragBase + mf * 1280 + ko);
            #pragma unroll
            for (int nfp = 0; nfp < 2; nfp++) {
                uint32_t bh[4], bl[4];
                ldsm4(bh, stBh + bFragBase + nfp * 1280 + ko);
                ldsm4(bl, stBl + bFragBase + nfp * 1280 + ko);
                #pragma unroll
                for (int mf = 0; mf < 4; mf++) {
                    mma16816(acc[mf][2 * nfp],     a[mf], bh);
                    mma16816(acc[mf][2 * nfp + 1], a[mf], bh + 2);
                    mma16816(acc[mf][2 * nfp],     a[mf], bl);
                    mma16816(acc[mf][2 * nfp + 1], a[mf], bl + 2);
                }
            }
            #pragma unroll
            for (int mf = 0; mf < 4; mf++)
                ldsm4(a[mf], stAl + aFragBase + mf * 1280 + ko);
            #pragma unroll
            for (int nfp = 0; nfp < 2; nfp++) {
                uint32_t bh[4];
                ldsm4(bh, stBh + bFragBase + nfp * 1280 + ko);
                #pragma unroll
                for (int mf = 0; mf < 4; mf++) {
                    mma16816(acc[mf][2 * nfp],     a[mf], bh);
                    mma16816(acc[mf][2 * nfp + 1], a[mf], bh + 2);
                }
            }
        }
        __syncthreads();
    }

    // ---- epilogue (batch pointer adjust deferred here to save regs) ----
    if (OUTM == 0) { Ohi += (size_t)b * 4096 * ldop; Olo += (size_t)b * 4096 * ldop; }
    float* oF = outF + (size_t)b * outFb;
    float* sst = (float*)smem;   // OUTM==2 staging (stages are dead now)

    #pragma unroll
    for (int mf = 0; mf < 4; mf++) {
        const int rl = m0w + mf * 16 + g;        // local row 0..127
        const int r0 = n0 + rl;
        #pragma unroll
        for (int nf = 0; nf < 4; nf++) {
            const int ncl = n0w + nf * 8 + t4 * 2;   // local col (even)
            const int ncol = c0 + ncl;
            float v00 = acc[mf][nf][0], v01 = acc[mf][nf][1];
            float v10 = acc[mf][nf][2], v11 = acc[mf][nf][3];
            if (BIASF) {
                const float b0f = bias[ncol], b1f = bias[ncol + 1];
                v00 += b0f; v01 += b1f; v10 += b0f; v11 += b1f;
            }
            if (SILU) {
                v00 = silu_f(v00); v01 = silu_f(v01);
                v10 = silu_f(v10); v11 = silu_f(v11);
            }
            if (OUTM == 0) {
                uint32_t hp, lp;
                pack2(v00, v01, hp, lp);
                const size_t i0 = (size_t)r0 * ldop + opbase + (ncol >> 1);
                Ohi[i0] = hp; Olo[i0] = lp;
                pack2(v10, v11, hp, lp);
                const size_t i1 = (size_t)(r0 + 8) * ldop + opbase + (ncol >> 1);
                Ohi[i1] = hp; Olo[i1] = lp;
            } else if (OUTM == 1) {
                *(float2*)(oF + (size_t)r0 * ldoutF + ncol)       = make_float2(v00, v01);
                *(float2*)(oF + (size_t)(r0 + 8) * ldoutF + ncol) = make_float2(v10, v11);
            } else {
                sst[ncl * 132 + rl]           = v00;
                sst[(ncl + 1) * 132 + rl]     = v01;
                sst[ncl * 132 + rl + 8]       = v10;
                sst[(ncl + 1) * 132 + rl + 8] = v11;
            }
        }
    }
    if (OUTM == 2) {
        __syncthreads();
        #pragma unroll
        for (int rnd = 0; rnd < 16; rnd++) {
            const int c = wid * 16 + rnd;
            float4 v = *(float4*)&sst[c * 132 + lane * 4];
            *(float4*)(oF + (size_t)(c0 + c) * ldoutF + n0 + lane * 4) = v;
        }
    }
}

// ---------------------------------------------------------------------------
// One merged prepack kernel: all weights + fused projection weights + bias.
// ---------------------------------------------------------------------------
__global__ void prepack_all_k(
    const float* __restrict__ cv1_w, const float* __restrict__ cv2_w,
    const float* __restrict__ vproj_w, const float* __restrict__ off_w,
    const float* __restrict__ aw_w, const float* __restrict__ vproj_b,
    const float* __restrict__ off_b, const float* __restrict__ aw_b,
    const float* __restrict__ out_w,
    const float* __restrict__ mc0, const float* __restrict__ mc1,
    const float* __restrict__ mc2, const float* __restrict__ mc3,
    uint32_t* __restrict__ wcv1_h, uint32_t* __restrict__ wcv1_l,
    uint32_t* __restrict__ wcv2_h, uint32_t* __restrict__ wcv2_l,
    uint32_t* __restrict__ wpj_h,  uint32_t* __restrict__ wpj_l,
    uint32_t* __restrict__ wop_h,  uint32_t* __restrict__ wop_l,
    uint32_t* __restrict__ wc_h,   uint32_t* __restrict__ wc_l,
    float* __restrict__ biasc)
{
    const int idx = blockIdx.x * 256 + threadIdx.x;
    const int R0 = 512 * 256;
    const int R1 = R0 + 512 * 640;
    const int R2 = R1 + 384 * 128;
    const int R3 = R2 + 256 * 128;
    const int R4 = R3 + 4 * 256 * 1152;
    const int R5 = R4 + 384;
    if (idx < R0) {
        const int co = idx >> 8, kp = idx & 255;
        uint32_t hp, lp;
        pack2(cv1_w[(size_t)co * 512 + 2 * kp], cv1_w[(size_t)co * 512 + 2 * kp + 1], hp, lp);
        wcv1_h[idx] = hp; wcv1_l[idx] = lp;
    } else if (idx < R1) {
        const int j = idx - R0, co = j / 640, kp = j - co * 640;
        uint32_t hp, lp;
        pack2(cv2_w[(size_t)co * 1280 + 2 * kp], cv2_w[(size_t)co * 1280 + 2 * kp + 1], hp, lp);
        wcv2_h[j] = hp; wcv2_l[j] = lp;
    } else if (idx < R2) {
        const int j = idx - R1, co = j >> 7, kp = j & 127;
        float v0 = 0.f, v1 = 0.f;
        if (co < 256)      { v0 = vproj_w[(size_t)(2*kp)*256 + co];     v1 = vproj_w[(size_t)(2*kp+1)*256 + co]; }
        else if (co < 320) { const int c = co - 256;
                             v0 = off_w[(size_t)(2*kp)*64 + c];         v1 = off_w[(size_t)(2*kp+1)*64 + c]; }
        else if (co < 352) { const int c = co - 320;
                             v0 = aw_w[(size_t)(2*kp)*32 + c];          v1 = aw_w[(size_t)(2*kp+1)*32 + c]; }
        uint32_t hp, lp; pack2(v0, v1, hp, lp);
        wpj_h[j] = hp; wpj_l[j] = lp;
    } else if (idx < R3) {
        const int j = idx - R2, co = j >> 7, kp = j & 127;
        uint32_t hp, lp;
        pack2(out_w[(size_t)(2*kp)*256 + co], out_w[(size_t)(2*kp+1)*256 + co], hp, lp);
        wop_h[j] = hp; wop_l[j] = lp;
    } else if (idx < R4) {
        const int j = idx - R3;
        const int which = j / (256 * 1152), r = j - which * (256 * 1152);
        const int co = r / 1152, kp = r - co * 1152;
        const int t = kp >> 7, cp = kp & 127;
        const float* W = which == 0 ? mc0 : which == 1 ? mc1 : which == 2 ? mc2 : mc3;
        uint32_t hp, lp;
        pack2(W[(size_t)co * 2304 + (2*cp)*9 + t], W[(size_t)co * 2304 + (2*cp+1)*9 + t], hp, lp);
        wc_h[j] = hp; wc_l[j] = lp;
    } else if (idx < R5) {
        const int j = idx - R4;
        biasc[j] = j < 256 ? vproj_b[j] : j < 320 ? off_b[j - 256]
                 : j < 352 ? aw_b[j - 320] : 0.f;
    }
}

// x (B,512,4096) -> packed [b*4096+n][256] via smem transpose
__global__ void prepack_x_k(const float* __restrict__ x,
                            uint32_t* __restrict__ xh, uint32_t* __restrict__ xl)
{
    __shared__ uint32_t th[32][33], tl[32][33];
    const int tx = threadIdx.x, ty = threadIdx.y;
    const int n0 = blockIdx.x * 32, cp0 = blockIdx.y * 32, b = blockIdx.z;
    const float* xb = x + (size_t)b * 512 * 4096;
    #pragma unroll
    for (int k = 0; k < 4; k++) {
        const int cp = cp0 + ty + k * 8;
        const float v0 = xb[(size_t)(2 * cp) * 4096 + n0 + tx];
        const float v1 = xb[(size_t)(2 * cp + 1) * 4096 + n0 + tx];
        uint32_t hp, lp; pack2(v0, v1, hp, lp);
        th[ty + k * 8][tx] = hp; tl[ty + k * 8][tx] = lp;
    }
    __syncthreads();
    #pragma unroll
    for (int k = 0; k < 4; k++) {
        const int n = n0 + ty + k * 8;
        const size_t o = ((size_t)b * 4096 + n) * 256 + cp0 + tx;
        xh[o] = th[tx][ty + k * 8];
        xl[o] = tl[tx][ty + k * 8];
    }
}

// ---------------------------------------------------------------------------
// Deformable sampling from fused projection buffer -> packed hi/lo output
// pj row layout: [val 0..255 | off 256..319 | aw 320..351 | pad], stride 384
// ---------------------------------------------------------------------------
__global__ void __launch_bounds__(256) msda_sample_k(
    const float* __restrict__ pj, const float* __restrict__ bbox,
    uint32_t* __restrict__ smpH, uint32_t* __restrict__ smpL)
{
    const int bl   = blockIdx.x;
    const int h    = threadIdx.x >> 5;
    const int lane = threadIdx.x & 31;
    const float* offp = pj + (size_t)bl * 384 + 256 + h * 8;
    const float* awp  = pj + (size_t)bl * 384 + 320 + h * 4;
    const float bx = bbox[(size_t)bl * 2 + 0];
    const float by = bbox[(size_t)bl * 2 + 1];

    float a0 = awp[0], a1 = awp[1], a2 = awp[2], a3 = awp[3];
    float mx = fmaxf(fmaxf(a0, a1), fmaxf(a2, a3));
    float e0 = __expf(a0 - mx), e1 = __expf(a1 - mx);
    float e2 = __expf(a2 - mx), e3 = __expf(a3 - mx);
    float inv = 1.f / (e0 + e1 + e2 + e3);
    float awv[4] = {e0 * inv, e1 * inv, e2 * inv, e3 * inv};

    const int b = bl >> 12;
    const float* vb = pj + (size_t)b * 4096 * 384 + h * 32 + lane;
    float acc = 0.f;
    #pragma unroll
    for (int p = 0; p < 4; p++) {
        float gx = (bx + offp[p * 2 + 0] * (1.f / 64.f)) * 64.f - 0.5f;
        float gy = (by + offp[p * 2 + 1] * (1.f / 64.f)) * 64.f - 0.5f;
        float x0f = floorf(gx), y0f = floorf(gy);
        float wx1 = gx - x0f, wy1 = gy - y0f;
        float wx0 = 1.f - wx1, wy0 = 1.f - wy1;
        int x0 = (int)x0f, y0 = (int)y0f;
        float s = 0.f;
        if ((unsigned)x0 < 64u && (unsigned)y0 < 64u)
            s += wx0 * wy0 * vb[(size_t)(y0 * 64 + x0) * 384];
        if ((unsigned)(x0 + 1) < 64u && (unsigned)y0 < 64u)
            s += wx1 * wy0 * vb[(size_t)(y0 * 64 + x0 + 1) * 384];
        if ((unsigned)x0 < 64u && (unsigned)(y0 + 1) < 64u)
            s += wx0 * wy1 * vb[(size_t)((y0 + 1) * 64 + x0) * 384];
        if ((unsigned)(x0 + 1) < 64u && (unsigned)(y0 + 1) < 64u)
            s += wx1 * wy1 * vb[(size_t)((y0 + 1) * 64 + x0 + 1) * 384];
        acc += awv[p] * s;
    }
    const float vOdd = __shfl_down_sync(0xffffffffu, acc, 1);
    if ((lane & 1) == 0) {
        uint32_t hp, lp; pack2(acc, vOdd, hp, lp);
        const size_t o = (size_t)bl * 128 + h * 16 + (lane >> 1);
        smpH[o] = hp; smpL[o] = lp;
    }
}

// ---------------------------------------------------------------------------
extern "C" void kernel_launch(void* const* d_in, const int* in_sizes, int n_in,
                              void* d_out, int out_size)
{
    const float* x       = (const float*)d_in[0];
    const float* bbox    = (const float*)d_in[1];
    const float* cv1_w   = (const float*)d_in[3];
    const float* mc0     = (const float*)d_in[4];
    const float* mc1     = (const float*)d_in[5];
    const float* mc2     = (const float*)d_in[6];
    const float* mc3     = (const float*)d_in[7];
    const float* vproj_w = (const float*)d_in[8];
    const float* vproj_b = (const float*)d_in[9];
    const float* off_w   = (const float*)d_in[10];
    const float* off_b   = (const float*)d_in[11];
    const float* aw_w    = (const float*)d_in[12];
    const float* aw_b    = (const float*)d_in[13];
    const float* out_w   = (const float*)d_in[14];
    const float* out_b   = (const float*)d_in[15];
    const float* cv2_w   = (const float*)d_in[16];
    float* out = (float*)d_out;

    uint32_t *xp_h, *xp_l, *catp_h, *catp_l, *s0p_h, *s0p_l, *smpp_h, *smpp_l;
    uint32_t *wcv1_h, *wcv1_l, *wcv2_h, *wcv2_l, *wpj_h, *wpj_l, *wop_h, *wop_l;
    uint32_t *wc_h, *wc_l;
    float *pj, *biasc;
    cudaGetSymbolAddress((void**)&xp_h, g_xp_h);   cudaGetSymbolAddress((void**)&xp_l, g_xp_l);
    cudaGetSymbolAddress((void**)&catp_h, g_catp_h); cudaGetSymbolAddress((void**)&catp_l, g_catp_l);
    cudaGetSymbolAddress((void**)&s0p_h, g_s0p_h); cudaGetSymbolAddress((void**)&s0p_l, g_s0p_l);
    cudaGetSymbolAddress((void**)&smpp_h, g_smpp_h); cudaGetSymbolAddress((void**)&smpp_l, g_smpp_l);
    cudaGetSymbolAddress((void**)&wcv1_h, g_wcv1_h); cudaGetSymbolAddress((void**)&wcv1_l, g_wcv1_l);
    cudaGetSymbolAddress((void**)&wcv2_h, g_wcv2_h); cudaGetSymbolAddress((void**)&wcv2_l, g_wcv2_l);
    cudaGetSymbolAddress((void**)&wpj_h, g_wpj_h); cudaGetSymbolAddress((void**)&wpj_l, g_wpj_l);
    cudaGetSymbolAddress((void**)&wop_h, g_wop_h); cudaGetSymbolAddress((void**)&wop_l, g_wop_l);
    cudaGetSymbolAddress((void**)&wc_h, g_wc_h);   cudaGetSymbolAddress((void**)&wc_l, g_wc_l);
    cudaGetSymbolAddress((void**)&pj, g_pj);
    cudaGetSymbolAddress((void**)&biasc, g_biasc);

    const int DYN = 2 * STAGE_B;   // 81920
    cudaFuncSetAttribute(mm_hmma<false,0,true ,false>, cudaFuncAttributeMaxDynamicSharedMemorySize, DYN);
    cudaFuncSetAttribute(mm_hmma<true ,0,true ,false>, cudaFuncAttributeMaxDynamicSharedMemorySize, DYN);
    cudaFuncSetAttribute(mm_hmma<false,1,false,true >, cudaFuncAttributeMaxDynamicSharedMemorySize, DYN);
    cudaFuncSetAttribute(mm_hmma<false,0,false,true >, cudaFuncAttributeMaxDynamicSharedMemorySize, DYN);
    cudaFuncSetAttribute(mm_hmma<false,2,true ,false>, cudaFuncAttributeMaxDynamicSharedMemorySize, DYN);

    // launch 0: all weight prepack + fused bias
    {
        const int total = 512*256 + 512*640 + 384*128 + 256*128 + 4*256*1152 + 384;
        prepack_all_k<<<(total + 255) / 256, 256>>>(
            cv1_w, cv2_w, vproj_w, off_w, aw_w, vproj_b, off_b, aw_b, out_w,
            mc0, mc1, mc2, mc3,
            wcv1_h, wcv1_l, wcv2_h, wcv2_l, wpj_h, wpj_l, wop_h, wop_l,
            wc_h, wc_l, biasc);
    }
    // launch 1: input prepack
    prepack_x_k<<<dim3(128, 8, NB), dim3(32, 8)>>>(x, xp_h, xp_l);

    // launch 2: cv1 -> cat [a|b] (pairs 0..255), SiLU
    mm_hmma<false,0,true,false><<<dim3(32, 4, NB), 256, DYN>>>(
        xp_h, xp_l, 256, 0, wcv1_h, wcv1_l, 256, nullptr,
        nullptr, 0, 0, catp_h, catp_l, 640, 0, 512);

    // launches 3-6: bottleneck convs b -> b1 -> b2
    mm_hmma<true,0,true,false><<<dim3(32, 2, NB), 256, DYN>>>(
        catp_h, catp_l, 640, 128, wc_h + 0*256*1152, wc_l + 0*256*1152, 1152, nullptr,
        nullptr, 0, 0, s0p_h, s0p_l, 128, 0, 2304);
    mm_hmma<true,0,true,false><<<dim3(32, 2, NB), 256, DYN>>>(
        s0p_h, s0p_l, 128, 0, wc_h + 1*256*1152, wc_l + 1*256*1152, 1152, nullptr,
        nullptr, 0, 0, catp_h, catp_l, 640, 256, 2304);
    mm_hmma<true,0,true,false><<<dim3(32, 2, NB), 256, DYN>>>(
        catp_h, catp_l, 640, 256, wc_h + 2*256*1152, wc_l + 2*256*1152, 1152, nullptr,
        nullptr, 0, 0, s0p_h, s0p_l, 128, 0, 2304);
    mm_hmma<true,0,true,false><<<dim3(32, 2, NB), 256, DYN>>>(
        s0p_h, s0p_l, 128, 0, wc_h + 3*256*1152, wc_l + 3*256*1152, 1152, nullptr,
        nullptr, 0, 0, catp_h, catp_l, 640, 384, 2304);

    // launch 7: fused projections (val|off|aw), fp32 out [row][384] + bias
    mm_hmma<false,1,false,true><<<dim3(32, 3, NB), 256, DYN>>>(
        catp_h, catp_l, 640, 384, wpj_h, wpj_l, 128, biasc,
        pj, 384, 4096L*384, nullptr, nullptr, 0, 0, 256);

    // launch 8: deformable sampling -> packed smp
    msda_sample_k<<<NB * HWN, 256>>>(pj, bbox, smpp_h, smpp_l);

    // launch 9: output projection -> cat attn section (pairs 512..639)
    mm_hmma<false,0,false,true><<<dim3(32, 2, NB), 256, DYN>>>(
        smpp_h, smpp_l, 128, 0, wop_h, wop_l, 128, out_b,
        nullptr, 0, 0, catp_h, catp_l, 640, 512, 256);

    // launch 10: cv2 K=1280, SiLU, channel-major fp32 out (coalesced via smem)
    mm_hmma<false,2,true,false><<<dim3(32, 4, NB), 256, DYN>>>(
        catp_h, catp_l, 640, 0, wcv2_h, wcv2_l, 640, nullptr,
        out, 4096, 512L*4096, nullptr, nullptr, 0, 0, 1280);
}